// round 5
// baseline (speedup 1.0000x reference)
#include <cuda_runtime.h>
#include <cuda_bf16.h>
#include <cstdint>

#define K_DIM 4096
#define N_DIM 4096
#define M_DIM 16384
#define NUM_VEC ((N_DIM * K_DIM) / 8)

// Scratch (__device__ globals; allocation-free rule)
__device__ float  g_qw[(size_t)N_DIM * K_DIM];         // fp32 q_weight
__device__ int8_t g_w1[(size_t)N_DIM * K_DIM];
__device__ int8_t g_w2[(size_t)N_DIM * K_DIM];
__device__ int8_t g_x1[(size_t)M_DIM * K_DIM];
__device__ int8_t g_x2[(size_t)M_DIM * K_DIM];
__device__ float  g_sx[M_DIM];
__device__ float  g_sw[N_DIM];

// ===========================================================================
// Kernel 1: VPTQ quantize weight -> q_weight (fp32)
// ===========================================================================
__global__ void quantize_w(const float* __restrict__ weight,
                           const float* __restrict__ centroids) {
    __shared__ float sc[2048];
    __shared__ float scc[256];
    const int tid = threadIdx.x;
    for (int i = tid; i < 2048; i += 256) sc[i] = centroids[i];
    __syncthreads();
    if (tid < 256) {
        float s = 0.f;
#pragma unroll
        for (int j = 0; j < 8; ++j) { float c = sc[tid * 8 + j]; s += c * c; }
        scc[tid] = s;
    }
    __syncthreads();

    const int v = blockIdx.x * 256 + tid;
    const float4* wv = reinterpret_cast<const float4*>(weight + (size_t)v * 8);
    float4 v0 = wv[0], v1 = wv[1];
    float vec[8] = {v0.x, v0.y, v0.z, v0.w, v1.x, v1.y, v1.z, v1.w};

    float vv = 0.f;
#pragma unroll
    for (int j = 0; j < 8; ++j) vv += vec[j] * vec[j];
    float norm = __fsqrt_rn(vv) + 1e-8f;

    float nrm[8];
#pragma unroll
    for (int j = 0; j < 8; ++j) nrm[j] = __fdiv_rn(vec[j], norm);
    float nn = 0.f;
#pragma unroll
    for (int j = 0; j < 8; ++j) nn += nrm[j] * nrm[j];

    int best = 0; float bestd = 3.402823e38f;
#pragma unroll 4
    for (int k = 0; k < 256; ++k) {
        const float4* c4 = reinterpret_cast<const float4*>(sc + k * 8);
        float4 c0 = c4[0], c1 = c4[1];
        float dot = nrm[0] * c0.x + nrm[1] * c0.y + nrm[2] * c0.z + nrm[3] * c0.w
                  + nrm[4] * c1.x + nrm[5] * c1.y + nrm[6] * c1.z + nrm[7] * c1.w;
        float d2 = nn - 2.0f * dot + scc[k];
        if (d2 < bestd) { bestd = d2; best = k; }
    }

    const float* cb = sc + best * 8;
    float cd = 0.f;
#pragma unroll
    for (int j = 0; j < 8; ++j) cd += vec[j] * cb[j];
    float scale = __fdiv_rn(cd, scc[best] + 1e-8f);

    float4 q0, q1;
    q0.x = cb[0] * scale; q0.y = cb[1] * scale; q0.z = cb[2] * scale; q0.w = cb[3] * scale;
    q1.x = cb[4] * scale; q1.y = cb[5] * scale; q1.z = cb[6] * scale; q1.w = cb[7] * scale;
    float4* out = reinterpret_cast<float4*>(g_qw + (size_t)v * 8);
    out[0] = q0; out[1] = q1;
}

// ===========================================================================
// Kernel 2: per-row 2-term int8 quantization (rows of 4096 fp32)
//   src row -> s = rowmax/127;  a1 = rint(v/s); a2 = rint((v/s - a1)*128)
// ===========================================================================
__global__ __launch_bounds__(256) void rowquant(const float* __restrict__ src,
                                                int8_t* __restrict__ q1,
                                                int8_t* __restrict__ q2,
                                                float* __restrict__ sc) {
    const int row = blockIdx.x;
    const int tid = threadIdx.x;
    const float4* s4 = reinterpret_cast<const float4*>(src + (size_t)row * 4096);

    float4 v[4];
    float m = 0.f;
#pragma unroll
    for (int j = 0; j < 4; ++j) {
        v[j] = s4[tid + 256 * j];
        m = fmaxf(m, fmaxf(fmaxf(fabsf(v[j].x), fabsf(v[j].y)),
                           fmaxf(fabsf(v[j].z), fabsf(v[j].w))));
    }
#pragma unroll
    for (int o = 16; o; o >>= 1) m = fmaxf(m, __shfl_xor_sync(0xffffffffu, m, o));
    __shared__ float red[8];
    if ((tid & 31) == 0) red[tid >> 5] = m;
    __syncthreads();
    float rm = red[0];
#pragma unroll
    for (int w = 1; w < 8; ++w) rm = fmaxf(rm, red[w]);

    const float s = rm * (1.0f / 127.0f) + 1e-30f;
    const float inv = 1.0f / s;
    if (tid == 0) sc[row] = s;

    uint32_t* q1w = reinterpret_cast<uint32_t*>(q1 + (size_t)row * 4096);
    uint32_t* q2w = reinterpret_cast<uint32_t*>(q2 + (size_t)row * 4096);
#pragma unroll
    for (int j = 0; j < 4; ++j) {
        const float f[4] = {v[j].x, v[j].y, v[j].z, v[j].w};
        uint32_t p1 = 0, p2 = 0;
#pragma unroll
        for (int e = 0; e < 4; ++e) {
            float t = f[e] * inv;
            int a1 = __float2int_rn(t);
            int a2 = __float2int_rn((t - (float)a1) * 128.0f);
            p1 |= ((uint32_t)a1 & 0xFFu) << (8 * e);
            p2 |= ((uint32_t)a2 & 0xFFu) << (8 * e);
        }
        q1w[tid + 256 * j] = p1;
        q2w[tid + 256 * j] = p2;
    }
}

// ===========================================================================
// Kernel 3: int8 GEMM  Y = sx*sw*(A1B1 + (A1B2+A2B1)/128) + bias
// CTA 128x128xK128(bytes), 256 thr (8 warps 2x4, warp tile 64x32),
// ldmatrix b16 on int8 bytes, 3-stage cp.async pipeline.
// ===========================================================================
#define BM 128
#define BN 128
#define BKB 128                         // K bytes per stage
#define SKB 144                         // padded row stride (bytes)
#define NKT (K_DIM / BKB)               // 32
#define AST (BM * SKB)                  // 18432 B per var buffer
#define STAGE_BYTES (4 * AST)           // A1,A2,B1,B2 = 73728
#define NSTAGE 3
#define SMEM_BYTES (NSTAGE * STAGE_BYTES)  // 221184

__device__ __forceinline__ void cp16(uint32_t saddr, const void* g) {
    asm volatile("cp.async.cg.shared.global [%0], [%1], 16;\n" ::"r"(saddr), "l"(g));
}
__device__ __forceinline__ void ldsm4(uint32_t* r, uint32_t addr) {
    asm volatile("ldmatrix.sync.aligned.m8n8.x4.shared.b16 {%0,%1,%2,%3}, [%4];"
                 : "=r"(r[0]), "=r"(r[1]), "=r"(r[2]), "=r"(r[3]) : "r"(addr));
}
__device__ __forceinline__ void imma(int* c, const uint32_t* a, const uint32_t* b) {
    asm volatile(
        "mma.sync.aligned.m16n8k32.row.col.s32.s8.s8.s32 "
        "{%0,%1,%2,%3}, {%4,%5,%6,%7}, {%8,%9}, {%0,%1,%2,%3};\n"
        : "+r"(c[0]), "+r"(c[1]), "+r"(c[2]), "+r"(c[3])
        : "r"(a[0]), "r"(a[1]), "r"(a[2]), "r"(a[3]), "r"(b[0]), "r"(b[1]));
}

__global__ __launch_bounds__(256, 1) void gemm_i8(const float* __restrict__ bias,
                                                  float* __restrict__ Y) {
    extern __shared__ int8_t sm8[];
    const uint32_t s0 = (uint32_t)__cvta_generic_to_shared(sm8);

    const int tid = threadIdx.x;
    const int wid = tid >> 5, lane = tid & 31;
    const int wm = wid >> 2, wn = wid & 3;       // 2 x 4 warps, warp tile 64x32
    const int m0 = blockIdx.y * BM, n0 = blockIdx.x * BN;

    int acc_a[4][4][4], acc_b[4][4][4];
#pragma unroll
    for (int i = 0; i < 4; ++i)
#pragma unroll
        for (int j = 0; j < 4; ++j)
#pragma unroll
            for (int r = 0; r < 4; ++r) { acc_a[i][j][r] = 0; acc_b[i][j][r] = 0; }

    const int t8 = lane >> 3, rr = lane & 7;
    const int a_row = (t8 & 1) * 8 + rr;
    const int a_cb = (t8 >> 1) * 16;             // byte offset
    const int b_row = (t8 >> 1) * 8 + rr;
    const int b_cb = (t8 & 1) * 16;

    auto load_stage = [&](int st, int kt) {
        const int k0 = kt * BKB;
        const uint32_t base = s0 + (uint32_t)st * STAGE_BYTES;
#pragma unroll
        for (int j = 0; j < 4; ++j) {
            const int idx = tid + j * 256;
            const int row = idx >> 3, c = idx & 7;
            const uint32_t so = (uint32_t)(row * SKB + c * 16);
            const size_t gA = (size_t)(m0 + row) * K_DIM + k0 + c * 16;
            const size_t gB = (size_t)(n0 + row) * K_DIM + k0 + c * 16;
            cp16(base + so, g_x1 + gA);
            cp16(base + AST + so, g_x2 + gA);
            cp16(base + 2 * AST + so, g_w1 + gB);
            cp16(base + 3 * AST + so, g_w2 + gB);
        }
    };

    load_stage(0, 0);
    asm volatile("cp.async.commit_group;\n");
    load_stage(1, 1);
    asm volatile("cp.async.commit_group;\n");

    for (int kt = 0; kt < NKT; ++kt) {
        const int st = kt % 3;
        __syncthreads();   // all warps done with buffer (kt+2)%3 (used at kt-1)
        if (kt + 2 < NKT) {
            load_stage((kt + 2) % 3, kt + 2);
            asm volatile("cp.async.commit_group;\n");
            asm volatile("cp.async.wait_group 2;\n");
        } else if (kt + 1 < NKT) {
            asm volatile("cp.async.wait_group 1;\n");
        } else {
            asm volatile("cp.async.wait_group 0;\n");
        }
        __syncthreads();   // stage st visible to all warps

        const uint32_t bA1 = s0 + (uint32_t)st * STAGE_BYTES;
        const uint32_t bA2 = bA1 + AST;
        const uint32_t bB1 = bA1 + 2 * AST;
        const uint32_t bB2 = bA1 + 3 * AST;

#pragma unroll
        for (int ks = 0; ks < 4; ++ks) {
            const int kc = ks * 32;
            uint32_t a1[4][4], a2[4][4];
#pragma unroll
            for (int i = 0; i < 4; ++i) {
                const uint32_t off =
                    (uint32_t)((wm * 64 + i * 16 + a_row) * SKB + kc + a_cb);
                ldsm4(a1[i], bA1 + off);
                ldsm4(a2[i], bA2 + off);
            }
            uint32_t b1[4][2], b2[4][2];
#pragma unroll
            for (int p = 0; p < 2; ++p) {
                const uint32_t off =
                    (uint32_t)((wn * 32 + p * 16 + b_row) * SKB + kc + b_cb);
                uint32_t u[4], w[4];
                ldsm4(u, bB1 + off);
                ldsm4(w, bB2 + off);
                b1[2 * p][0] = u[0]; b1[2 * p][1] = u[1];
                b1[2 * p + 1][0] = u[2]; b1[2 * p + 1][1] = u[3];
                b2[2 * p][0] = w[0]; b2[2 * p][1] = w[1];
                b2[2 * p + 1][0] = w[2]; b2[2 * p + 1][1] = w[3];
            }
#pragma unroll
            for (int i = 0; i < 4; ++i)
#pragma unroll
                for (int j = 0; j < 4; ++j) {
                    imma(acc_a[i][j], a1[i], b1[j]);   // a1*b1
                    imma(acc_b[i][j], a1[i], b2[j]);   // a1*b2
                    imma(acc_b[i][j], a2[i], b1[j]);   // a2*b1
                }
        }
    }

    // ---- epilogue: Y = sx*sw*(acc_a + acc_b/128) + bias ----
    const int g = lane >> 2, t = lane & 3;
#pragma unroll
    for (int i = 0; i < 4; ++i) {
#pragma unroll
        for (int j = 0; j < 4; ++j) {
            const int row = m0 + wm * 64 + i * 16 + g;
            const int col = n0 + wn * 32 + j * 8 + t * 2;
            const float sx0 = __ldg(&g_sx[row]);
            const float sx1 = __ldg(&g_sx[row + 8]);
            const float sw0 = __ldg(&g_sw[col]);
            const float sw1 = __ldg(&g_sw[col + 1]);
            const float b0 = __ldg(&bias[col]);
            const float b1v = __ldg(&bias[col + 1]);
            const int* pa = acc_a[i][j];
            const int* pb = acc_b[i][j];
            float2 r0, r1;
            r0.x = sx0 * sw0 * ((float)pa[0] + (float)pb[0] * 0.0078125f) + b0;
            r0.y = sx0 * sw1 * ((float)pa[1] + (float)pb[1] * 0.0078125f) + b1v;
            r1.x = sx1 * sw0 * ((float)pa[2] + (float)pb[2] * 0.0078125f) + b0;
            r1.y = sx1 * sw1 * ((float)pa[3] + (float)pb[3] * 0.0078125f) + b1v;
            *reinterpret_cast<float2*>(&Y[(size_t)row * N_DIM + col]) = r0;
            *reinterpret_cast<float2*>(&Y[(size_t)(row + 8) * N_DIM + col]) = r1;
        }
    }
}

// ===========================================================================
extern "C" void kernel_launch(void* const* d_in, const int* in_sizes, int n_in,
                              void* d_out, int out_size) {
    const float* x = (const float*)d_in[0];
    const float* weight = (const float*)d_in[1];
    const float* bias = (const float*)d_in[2];
    const float* centroids = (const float*)d_in[3];
    float* Y = (float*)d_out;

    void *pqw = nullptr, *pw1 = nullptr, *pw2 = nullptr, *px1 = nullptr, *px2 = nullptr;
    void *psx = nullptr, *psw = nullptr;
    cudaGetSymbolAddress(&pqw, g_qw);
    cudaGetSymbolAddress(&pw1, g_w1);
    cudaGetSymbolAddress(&pw2, g_w2);
    cudaGetSymbolAddress(&px1, g_x1);
    cudaGetSymbolAddress(&px2, g_x2);
    cudaGetSymbolAddress(&psx, g_sx);
    cudaGetSymbolAddress(&psw, g_sw);

    quantize_w<<<NUM_VEC / 256, 256>>>(weight, centroids);
    rowquant<<<N_DIM, 256>>>((const float*)pqw, (int8_t*)pw1, (int8_t*)pw2, (float*)psw);
    rowquant<<<M_DIM, 256>>>(x, (int8_t*)px1, (int8_t*)px2, (float*)psx);

    cudaFuncSetAttribute(gemm_i8, cudaFuncAttributeMaxDynamicSharedMemorySize, SMEM_BYTES);
    dim3 grid(N_DIM / BN, M_DIM / BM);   // (32, 128)
    gemm_i8<<<grid, 256, SMEM_BYTES>>>(bias, Y);
}

// round 6
// speedup vs baseline: 5.9675x; 5.9675x over previous
#include <cuda_runtime.h>
#include <cuda_fp16.h>
#include <cstdint>

#define K_DIM 4096
#define N_DIM 4096
#define M_DIM 16384
#define NUM_VEC ((N_DIM * K_DIM) / 8)

// Scratch (__device__ globals; allocation-free rule)
__device__ __half g_wh[(size_t)N_DIM * K_DIM];   // fp16 q_weight
__device__ __half g_xh[(size_t)M_DIM * K_DIM];   // fp16 x

// ===========================================================================
// Kernel 1: VPTQ quantize weight -> q_weight, emit fp16 directly
// ===========================================================================
__global__ void quantize_w(const float* __restrict__ weight,
                           const float* __restrict__ centroids) {
    __shared__ float sc[2048];
    __shared__ float scc[256];
    const int tid = threadIdx.x;
    for (int i = tid; i < 2048; i += 256) sc[i] = centroids[i];
    __syncthreads();
    if (tid < 256) {
        float s = 0.f;
#pragma unroll
        for (int j = 0; j < 8; ++j) { float c = sc[tid * 8 + j]; s += c * c; }
        scc[tid] = s;
    }
    __syncthreads();

    const int v = blockIdx.x * 256 + tid;
    const float4* wv = reinterpret_cast<const float4*>(weight + (size_t)v * 8);
    float4 v0 = wv[0], v1 = wv[1];
    float vec[8] = {v0.x, v0.y, v0.z, v0.w, v1.x, v1.y, v1.z, v1.w};

    float vv = 0.f;
#pragma unroll
    for (int j = 0; j < 8; ++j) vv += vec[j] * vec[j];
    float norm = __fsqrt_rn(vv) + 1e-8f;

    float nrm[8];
#pragma unroll
    for (int j = 0; j < 8; ++j) nrm[j] = __fdiv_rn(vec[j], norm);
    float nn = 0.f;
#pragma unroll
    for (int j = 0; j < 8; ++j) nn += nrm[j] * nrm[j];

    int best = 0; float bestd = 3.402823e38f;
#pragma unroll 4
    for (int k = 0; k < 256; ++k) {
        const float4* c4 = reinterpret_cast<const float4*>(sc + k * 8);
        float4 c0 = c4[0], c1 = c4[1];
        float dot = nrm[0] * c0.x + nrm[1] * c0.y + nrm[2] * c0.z + nrm[3] * c0.w
                  + nrm[4] * c1.x + nrm[5] * c1.y + nrm[6] * c1.z + nrm[7] * c1.w;
        float d2 = nn - 2.0f * dot + scc[k];
        if (d2 < bestd) { bestd = d2; best = k; }
    }

    const float* cb = sc + best * 8;
    float cd = 0.f;
#pragma unroll
    for (int j = 0; j < 8; ++j) cd += vec[j] * cb[j];
    float scale = __fdiv_rn(cd, scc[best] + 1e-8f);

    union { __half h[8]; uint4 u; } ph;
#pragma unroll
    for (int j = 0; j < 8; ++j) ph.h[j] = __float2half_rn(cb[j] * scale);
    reinterpret_cast<uint4*>(g_wh)[v] = ph.u;
}

// ===========================================================================
// Kernel 2: x -> fp16
// ===========================================================================
__global__ void convert_x(const float* __restrict__ x) {
    const size_t gid = (size_t)blockIdx.x * 256 + threadIdx.x;
    float4 v = reinterpret_cast<const float4*>(x)[gid];
    union { __half2 h2[2]; uint2 u; } p;
    p.h2[0] = __floats2half2_rn(v.x, v.y);
    p.h2[1] = __floats2half2_rn(v.z, v.w);
    reinterpret_cast<uint2*>(g_xh)[gid] = p.u;
}

// ===========================================================================
// Kernel 3: fp16 GEMM  Y[M,N] = Xh @ Wh^T + bias   (fp32 accum)
// CTA 128x256x64, 256 thr (8 warps 2x4, warp tile 64x64), ldmatrix,
// 4-stage cp.async pipeline, ONE sync per kt.
// ===========================================================================
#define BM 128
#define BN 256
#define BK 64
#define SKP 72                         // row stride in elems (144B), LDSM conflict-free
#define NKT (K_DIM / BK)               // 64
#define ABYTES (BM * SKP * 2)          // 18432
#define BBYTES (BN * SKP * 2)          // 36864
#define STG (ABYTES + BBYTES)          // 55296
#define NSTAGE 4
#define SMEM_BYTES (NSTAGE * STG)      // 221184

__device__ __forceinline__ void cp16(uint32_t saddr, const void* g) {
    asm volatile("cp.async.cg.shared.global [%0], [%1], 16;\n" ::"r"(saddr), "l"(g));
}
__device__ __forceinline__ void ldsm4(uint32_t* r, uint32_t addr) {
    asm volatile("ldmatrix.sync.aligned.m8n8.x4.shared.b16 {%0,%1,%2,%3}, [%4];"
                 : "=r"(r[0]), "=r"(r[1]), "=r"(r[2]), "=r"(r[3]) : "r"(addr));
}
__device__ __forceinline__ void hmma(float* c, const uint32_t* a, const uint32_t* b) {
    asm volatile(
        "mma.sync.aligned.m16n8k16.row.col.f32.f16.f16.f32 "
        "{%0,%1,%2,%3}, {%4,%5,%6,%7}, {%8,%9}, {%0,%1,%2,%3};\n"
        : "+f"(c[0]), "+f"(c[1]), "+f"(c[2]), "+f"(c[3])
        : "r"(a[0]), "r"(a[1]), "r"(a[2]), "r"(a[3]), "r"(b[0]), "r"(b[1]));
}

__global__ __launch_bounds__(256, 1) void gemm_f16(const float* __restrict__ bias,
                                                   float* __restrict__ Y) {
    extern __shared__ __half sm[];
    const uint32_t s0 = (uint32_t)__cvta_generic_to_shared(sm);

    const int tid = threadIdx.x;
    const int wid = tid >> 5, lane = tid & 31;
    const int wm = wid >> 2, wn = wid & 3;       // 2x4 warps, warp tile 64x64
    const int m0 = blockIdx.y * BM, n0 = blockIdx.x * BN;

    float acc[4][8][4];
#pragma unroll
    for (int i = 0; i < 4; ++i)
#pragma unroll
        for (int j = 0; j < 8; ++j)
#pragma unroll
            for (int r = 0; r < 4; ++r) acc[i][j][r] = 0.f;

    const int t8 = lane >> 3, rr = lane & 7;
    const int a_row = (t8 & 1) * 8 + rr;
    const int a_col = (t8 >> 1) * 8;
    const int b_row = (t8 >> 1) * 8 + rr;
    const int b_col = (t8 & 1) * 8;

    auto load_stage = [&](int st, int kt) {
        const int k0 = kt * BK;
        const uint32_t sA = s0 + (uint32_t)st * STG;
        const uint32_t sB = sA + ABYTES;
        // A: 128 rows x 8 chunks = 1024 -> 4/thread
#pragma unroll
        for (int j = 0; j < 4; ++j) {
            const int idx = tid + j * 256;
            const int row = idx >> 3, c = idx & 7;
            cp16(sA + (uint32_t)(row * SKP + c * 8) * 2u,
                 g_xh + (size_t)(m0 + row) * K_DIM + k0 + c * 8);
        }
        // B: 256 rows x 8 chunks = 2048 -> 8/thread
#pragma unroll
        for (int j = 0; j < 8; ++j) {
            const int idx = tid + j * 256;
            const int row = idx >> 3, c = idx & 7;
            cp16(sB + (uint32_t)(row * SKP + c * 8) * 2u,
                 g_wh + (size_t)(n0 + row) * K_DIM + k0 + c * 8);
        }
    };

    load_stage(0, 0); asm volatile("cp.async.commit_group;\n");
    load_stage(1, 1); asm volatile("cp.async.commit_group;\n");
    load_stage(2, 2); asm volatile("cp.async.commit_group;\n");

    for (int kt = 0; kt < NKT; ++kt) {
        const int st = kt & 3;
        // guarantee stage kt has arrived (exact tail counts)
        if (kt < NKT - 2)       asm volatile("cp.async.wait_group 2;\n");
        else if (kt == NKT - 2) asm volatile("cp.async.wait_group 1;\n");
        else                    asm volatile("cp.async.wait_group 0;\n");
        __syncthreads();   // data visible; all warps finished stage (kt+3)&3 compute
        if (kt + 3 < NKT) {
            load_stage((kt + 3) & 3, kt + 3);
            asm volatile("cp.async.commit_group;\n");
        }

        const uint32_t sA = s0 + (uint32_t)st * STG;
        const uint32_t sB = sA + ABYTES;

#pragma unroll
        for (int ks = 0; ks < 4; ++ks) {
            const int kc = ks * 16;
            uint32_t a[4][4], b[8][2];
#pragma unroll
            for (int i = 0; i < 4; ++i) {
                const uint32_t off =
                    (uint32_t)((wm * 64 + i * 16 + a_row) * SKP + kc + a_col) * 2u;
                ldsm4(a[i], sA + off);
            }
#pragma unroll
            for (int p = 0; p < 4; ++p) {
                const uint32_t off =
                    (uint32_t)((wn * 64 + p * 16 + b_row) * SKP + kc + b_col) * 2u;
                uint32_t u[4];
                ldsm4(u, sB + off);
                b[2 * p][0] = u[0]; b[2 * p][1] = u[1];
                b[2 * p + 1][0] = u[2]; b[2 * p + 1][1] = u[3];
            }
#pragma unroll
            for (int i = 0; i < 4; ++i)
#pragma unroll
                for (int j = 0; j < 8; ++j)
                    hmma(acc[i][j], a[i], b[j]);
        }
    }

    // ---- epilogue ----
    const int g = lane >> 2, t = lane & 3;
#pragma unroll
    for (int i = 0; i < 4; ++i) {
#pragma unroll
        for (int j = 0; j < 8; ++j) {
            const int row = m0 + wm * 64 + i * 16 + g;
            const int col = n0 + wn * 64 + j * 8 + t * 2;
            const float b0 = __ldg(&bias[col]);
            const float b1 = __ldg(&bias[col + 1]);
            float2 r0 = make_float2(acc[i][j][0] + b0, acc[i][j][1] + b1);
            float2 r1 = make_float2(acc[i][j][2] + b0, acc[i][j][3] + b1);
            *reinterpret_cast<float2*>(&Y[(size_t)row * N_DIM + col]) = r0;
            *reinterpret_cast<float2*>(&Y[(size_t)(row + 8) * N_DIM + col]) = r1;
        }
    }
}

// ===========================================================================
extern "C" void kernel_launch(void* const* d_in, const int* in_sizes, int n_in,
                              void* d_out, int out_size) {
    const float* x = (const float*)d_in[0];
    const float* weight = (const float*)d_in[1];
    const float* bias = (const float*)d_in[2];
    const float* centroids = (const float*)d_in[3];
    float* Y = (float*)d_out;

    quantize_w<<<NUM_VEC / 256, 256>>>(weight, centroids);
    convert_x<<<(int)(((size_t)M_DIM * K_DIM / 4) / 256), 256>>>(x);

    cudaFuncSetAttribute(gemm_f16, cudaFuncAttributeMaxDynamicSharedMemorySize, SMEM_BYTES);
    dim3 grid(N_DIM / BN, M_DIM / BM);   // (16, 128)
    gemm_f16<<<grid, 256, SMEM_BYTES>>>(bias, Y);
}

// round 7
// speedup vs baseline: 6.1042x; 1.0229x over previous
#include <cuda_runtime.h>
#include <cuda_fp16.h>
#include <cstdint>

#define K_DIM 4096
#define N_DIM 4096
#define M_DIM 16384
#define NUM_VEC ((N_DIM * K_DIM) / 8)

// Scratch (__device__ globals; allocation-free rule)
__device__ __half g_wh[(size_t)N_DIM * K_DIM];   // fp16 q_weight
__device__ __half g_xh[(size_t)M_DIM * K_DIM];   // fp16 x

// ===========================================================================
// Kernel 1: VPTQ quantize weight -> q_weight, emit fp16 directly
// ===========================================================================
__global__ void quantize_w(const float* __restrict__ weight,
                           const float* __restrict__ centroids) {
    __shared__ float sc[2048];
    __shared__ float scc[256];
    const int tid = threadIdx.x;
    for (int i = tid; i < 2048; i += 256) sc[i] = centroids[i];
    __syncthreads();
    if (tid < 256) {
        float s = 0.f;
#pragma unroll
        for (int j = 0; j < 8; ++j) { float c = sc[tid * 8 + j]; s += c * c; }
        scc[tid] = s;
    }
    __syncthreads();

    const int v = blockIdx.x * 256 + tid;
    const float4* wv = reinterpret_cast<const float4*>(weight + (size_t)v * 8);
    float4 v0 = wv[0], v1 = wv[1];
    float vec[8] = {v0.x, v0.y, v0.z, v0.w, v1.x, v1.y, v1.z, v1.w};

    float vv = 0.f;
#pragma unroll
    for (int j = 0; j < 8; ++j) vv += vec[j] * vec[j];
    float norm = __fsqrt_rn(vv) + 1e-8f;

    float nrm[8];
#pragma unroll
    for (int j = 0; j < 8; ++j) nrm[j] = __fdiv_rn(vec[j], norm);
    float nn = 0.f;
#pragma unroll
    for (int j = 0; j < 8; ++j) nn += nrm[j] * nrm[j];

    int best = 0; float bestd = 3.402823e38f;
#pragma unroll 4
    for (int k = 0; k < 256; ++k) {
        const float4* c4 = reinterpret_cast<const float4*>(sc + k * 8);
        float4 c0 = c4[0], c1 = c4[1];
        float dot = nrm[0] * c0.x + nrm[1] * c0.y + nrm[2] * c0.z + nrm[3] * c0.w
                  + nrm[4] * c1.x + nrm[5] * c1.y + nrm[6] * c1.z + nrm[7] * c1.w;
        float d2 = nn - 2.0f * dot + scc[k];
        if (d2 < bestd) { bestd = d2; best = k; }
    }

    const float* cb = sc + best * 8;
    float cd = 0.f;
#pragma unroll
    for (int j = 0; j < 8; ++j) cd += vec[j] * cb[j];
    float scale = __fdiv_rn(cd, scc[best] + 1e-8f);

    union { __half h[8]; uint4 u; } ph;
#pragma unroll
    for (int j = 0; j < 8; ++j) ph.h[j] = __float2half_rn(cb[j] * scale);
    reinterpret_cast<uint4*>(g_wh)[v] = ph.u;
}

// ===========================================================================
// Kernel 2: x -> fp16
// ===========================================================================
__global__ void convert_x(const float* __restrict__ x) {
    const size_t gid = (size_t)blockIdx.x * 256 + threadIdx.x;
    float4 v = reinterpret_cast<const float4*>(x)[gid];
    union { __half2 h2[2]; uint2 u; } p;
    p.h2[0] = __floats2half2_rn(v.x, v.y);
    p.h2[1] = __floats2half2_rn(v.z, v.w);
    reinterpret_cast<uint2*>(g_xh)[gid] = p.u;
}

// ===========================================================================
// Kernel 3: fp16 GEMM  Y[M,N] = Xh @ Wh^T + bias   (fp32 accum)
// CTA 128x256x64, 512 thr (16 warps 4x4, warp tile 32x64), ldmatrix,
// 4-stage cp.async pipeline, ONE sync per kt.
// ===========================================================================
#define BM 128
#define BN 256
#define BK 64
#define SKP 72                         // row stride in elems (144B), LDSM conflict-free
#define NKT (K_DIM / BK)               // 64
#define ABYTES (BM * SKP * 2)          // 18432
#define BBYTES (BN * SKP * 2)          // 36864
#define STG (ABYTES + BBYTES)          // 55296
#define NSTAGE 4
#define SMEM_BYTES (NSTAGE * STG)      // 221184
#define NTHR 512

__device__ __forceinline__ void cp16(uint32_t saddr, const void* g) {
    asm volatile("cp.async.cg.shared.global [%0], [%1], 16;\n" ::"r"(saddr), "l"(g));
}
__device__ __forceinline__ void ldsm4(uint32_t* r, uint32_t addr) {
    asm volatile("ldmatrix.sync.aligned.m8n8.x4.shared.b16 {%0,%1,%2,%3}, [%4];"
                 : "=r"(r[0]), "=r"(r[1]), "=r"(r[2]), "=r"(r[3]) : "r"(addr));
}
__device__ __forceinline__ void hmma(float* c, const uint32_t* a, const uint32_t* b) {
    asm volatile(
        "mma.sync.aligned.m16n8k16.row.col.f32.f16.f16.f32 "
        "{%0,%1,%2,%3}, {%4,%5,%6,%7}, {%8,%9}, {%0,%1,%2,%3};\n"
        : "+f"(c[0]), "+f"(c[1]), "+f"(c[2]), "+f"(c[3])
        : "r"(a[0]), "r"(a[1]), "r"(a[2]), "r"(a[3]), "r"(b[0]), "r"(b[1]));
}

__global__ __launch_bounds__(NTHR, 1) void gemm_f16(const float* __restrict__ bias,
                                                    float* __restrict__ Y) {
    extern __shared__ __half sm[];
    const uint32_t s0 = (uint32_t)__cvta_generic_to_shared(sm);

    const int tid = threadIdx.x;
    const int wid = tid >> 5, lane = tid & 31;
    const int wm = wid >> 2, wn = wid & 3;       // 4x4 warps, warp tile 32x64
    const int m0 = blockIdx.y * BM, n0 = blockIdx.x * BN;

    float acc[2][8][4];
#pragma unroll
    for (int i = 0; i < 2; ++i)
#pragma unroll
        for (int j = 0; j < 8; ++j)
#pragma unroll
            for (int r = 0; r < 4; ++r) acc[i][j][r] = 0.f;

    const int t8 = lane >> 3, rr = lane & 7;
    const int a_row = (t8 & 1) * 8 + rr;
    const int a_col = (t8 >> 1) * 8;
    const int b_row = (t8 >> 1) * 8 + rr;
    const int b_col = (t8 & 1) * 8;

    auto load_stage = [&](int st, int kt) {
        const int k0 = kt * BK;
        const uint32_t sA = s0 + (uint32_t)st * STG;
        const uint32_t sB = sA + ABYTES;
        // A: 128 rows x 8 chunks = 1024 -> 2/thread
#pragma unroll
        for (int j = 0; j < 2; ++j) {
            const int idx = tid + j * NTHR;
            const int row = idx >> 3, c = idx & 7;
            cp16(sA + (uint32_t)(row * SKP + c * 8) * 2u,
                 g_xh + (size_t)(m0 + row) * K_DIM + k0 + c * 8);
        }
        // B: 256 rows x 8 chunks = 2048 -> 4/thread
#pragma unroll
        for (int j = 0; j < 4; ++j) {
            const int idx = tid + j * NTHR;
            const int row = idx >> 3, c = idx & 7;
            cp16(sB + (uint32_t)(row * SKP + c * 8) * 2u,
                 g_wh + (size_t)(n0 + row) * K_DIM + k0 + c * 8);
        }
    };

    load_stage(0, 0); asm volatile("cp.async.commit_group;\n");
    load_stage(1, 1); asm volatile("cp.async.commit_group;\n");
    load_stage(2, 2); asm volatile("cp.async.commit_group;\n");

    for (int kt = 0; kt < NKT; ++kt) {
        const int st = kt & 3;
        if (kt < NKT - 2)       asm volatile("cp.async.wait_group 2;\n");
        else if (kt == NKT - 2) asm volatile("cp.async.wait_group 1;\n");
        else                    asm volatile("cp.async.wait_group 0;\n");
        __syncthreads();   // stage kt visible; all warps done with stage (kt+3)&3
        if (kt + 3 < NKT) {
            load_stage((kt + 3) & 3, kt + 3);
            asm volatile("cp.async.commit_group;\n");
        }

        const uint32_t sA = s0 + (uint32_t)st * STG;
        const uint32_t sB = sA + ABYTES;

#pragma unroll
        for (int ks = 0; ks < 4; ++ks) {
            const int kc = ks * 16;
            uint32_t a[2][4], b[8][2];
#pragma unroll
            for (int i = 0; i < 2; ++i) {
                const uint32_t off =
                    (uint32_t)((wm * 32 + i * 16 + a_row) * SKP + kc + a_col) * 2u;
                ldsm4(a[i], sA + off);
            }
#pragma unroll
            for (int p = 0; p < 4; ++p) {
                const uint32_t off =
                    (uint32_t)((wn * 64 + p * 16 + b_row) * SKP + kc + b_col) * 2u;
                uint32_t u[4];
                ldsm4(u, sB + off);
                b[2 * p][0] = u[0]; b[2 * p][1] = u[1];
                b[2 * p + 1][0] = u[2]; b[2 * p + 1][1] = u[3];
            }
#pragma unroll
            for (int i = 0; i < 2; ++i)
#pragma unroll
                for (int j = 0; j < 8; ++j)
                    hmma(acc[i][j], a[i], b[j]);
        }
    }

    // ---- epilogue ----
    const int g = lane >> 2, t = lane & 3;
#pragma unroll
    for (int i = 0; i < 2; ++i) {
#pragma unroll
        for (int j = 0; j < 8; ++j) {
            const int row = m0 + wm * 32 + i * 16 + g;
            const int col = n0 + wn * 64 + j * 8 + t * 2;
            const float b0 = __ldg(&bias[col]);
            const float b1 = __ldg(&bias[col + 1]);
            float2 r0 = make_float2(acc[i][j][0] + b0, acc[i][j][1] + b1);
            float2 r1 = make_float2(acc[i][j][2] + b0, acc[i][j][3] + b1);
            *reinterpret_cast<float2*>(&Y[(size_t)row * N_DIM + col]) = r0;
            *reinterpret_cast<float2*>(&Y[(size_t)(row + 8) * N_DIM + col]) = r1;
        }
    }
}

// ===========================================================================
extern "C" void kernel_launch(void* const* d_in, const int* in_sizes, int n_in,
                              void* d_out, int out_size) {
    const float* x = (const float*)d_in[0];
    const float* weight = (const float*)d_in[1];
    const float* bias = (const float*)d_in[2];
    const float* centroids = (const float*)d_in[3];
    float* Y = (float*)d_out;

    quantize_w<<<NUM_VEC / 256, 256>>>(weight, centroids);
    convert_x<<<(int)(((size_t)M_DIM * K_DIM / 4) / 256), 256>>>(x);

    cudaFuncSetAttribute(gemm_f16, cudaFuncAttributeMaxDynamicSharedMemorySize, SMEM_BYTES);
    dim3 grid(N_DIM / BN, M_DIM / BM);   // (16, 128)
    gemm_f16<<<grid, NTHR, SMEM_BYTES>>>(bias, Y);
}

// round 8
// speedup vs baseline: 6.1384x; 1.0056x over previous
#include <cuda_runtime.h>
#include <cuda_fp16.h>
#include <cstdint>

#define K_DIM 4096
#define N_DIM 4096
#define M_DIM 16384
#define NUM_VEC ((N_DIM * K_DIM) / 8)

// Scratch (__device__ globals; allocation-free rule)
__device__ __half g_wh[(size_t)N_DIM * K_DIM];   // fp16 q_weight
__device__ __half g_xh[(size_t)M_DIM * K_DIM];   // fp16 x

// ===========================================================================
// Kernel 1: VPTQ quantize weight -> q_weight, emit fp16 directly
// ===========================================================================
__global__ void quantize_w(const float* __restrict__ weight,
                           const float* __restrict__ centroids) {
    __shared__ float sc[2048];
    __shared__ float scc[256];
    const int tid = threadIdx.x;
    for (int i = tid; i < 2048; i += 256) sc[i] = centroids[i];
    __syncthreads();
    if (tid < 256) {
        float s = 0.f;
#pragma unroll
        for (int j = 0; j < 8; ++j) { float c = sc[tid * 8 + j]; s += c * c; }
        scc[tid] = s;
    }
    __syncthreads();

    const int v = blockIdx.x * 256 + tid;
    const float4* wv = reinterpret_cast<const float4*>(weight + (size_t)v * 8);
    float4 v0 = wv[0], v1 = wv[1];
    float vec[8] = {v0.x, v0.y, v0.z, v0.w, v1.x, v1.y, v1.z, v1.w};

    float vv = 0.f;
#pragma unroll
    for (int j = 0; j < 8; ++j) vv += vec[j] * vec[j];
    float norm = __fsqrt_rn(vv) + 1e-8f;

    float nrm[8];
#pragma unroll
    for (int j = 0; j < 8; ++j) nrm[j] = __fdiv_rn(vec[j], norm);
    float nn = 0.f;
#pragma unroll
    for (int j = 0; j < 8; ++j) nn += nrm[j] * nrm[j];

    int best = 0; float bestd = 3.402823e38f;
#pragma unroll 4
    for (int k = 0; k < 256; ++k) {
        const float4* c4 = reinterpret_cast<const float4*>(sc + k * 8);
        float4 c0 = c4[0], c1 = c4[1];
        float dot = nrm[0] * c0.x + nrm[1] * c0.y + nrm[2] * c0.z + nrm[3] * c0.w
                  + nrm[4] * c1.x + nrm[5] * c1.y + nrm[6] * c1.z + nrm[7] * c1.w;
        float d2 = nn - 2.0f * dot + scc[k];
        if (d2 < bestd) { bestd = d2; best = k; }
    }

    const float* cb = sc + best * 8;
    float cd = 0.f;
#pragma unroll
    for (int j = 0; j < 8; ++j) cd += vec[j] * cb[j];
    float scale = __fdiv_rn(cd, scc[best] + 1e-8f);

    union { __half h[8]; uint4 u; } ph;
#pragma unroll
    for (int j = 0; j < 8; ++j) ph.h[j] = __float2half_rn(cb[j] * scale);
    reinterpret_cast<uint4*>(g_wh)[v] = ph.u;
}

// ===========================================================================
// Kernel 2: x -> fp16
// ===========================================================================
__global__ void convert_x(const float* __restrict__ x) {
    const size_t gid = (size_t)blockIdx.x * 256 + threadIdx.x;
    float4 v = reinterpret_cast<const float4*>(x)[gid];
    union { __half2 h2[2]; uint2 u; } p;
    p.h2[0] = __floats2half2_rn(v.x, v.y);
    p.h2[1] = __floats2half2_rn(v.z, v.w);
    reinterpret_cast<uint2*>(g_xh)[gid] = p.u;
}

// ===========================================================================
// Kernel 3: fp16 GEMM  Y[M,N] = Xh @ Wh^T + bias   (fp32 accum)
// CTA 128x256x128, 256 thr (8 warps 2x4, warp tile 64x64), ldmatrix with
// explicit register double-buffering, 2-stage cp.async pipeline.
// ===========================================================================
#define BM 128
#define BN 256
#define BK 128
#define SKP 136                        // row stride in elems (272B), LDSM conflict-free
#define NKT (K_DIM / BK)               // 32
#define ABYTES (BM * SKP * 2)          // 34816
#define BBYTES (BN * SKP * 2)          // 69632
#define STG (ABYTES + BBYTES)          // 104448
#define SMEM_BYTES (2 * STG)           // 208896
#define NTHR 256

__device__ __forceinline__ void cp16(uint32_t saddr, const void* g) {
    asm volatile("cp.async.cg.shared.global [%0], [%1], 16;\n" ::"r"(saddr), "l"(g));
}
__device__ __forceinline__ void ldsm4(uint32_t* r, uint32_t addr) {
    asm volatile("ldmatrix.sync.aligned.m8n8.x4.shared.b16 {%0,%1,%2,%3}, [%4];"
                 : "=r"(r[0]), "=r"(r[1]), "=r"(r[2]), "=r"(r[3]) : "r"(addr));
}
__device__ __forceinline__ void hmma(float* c, const uint32_t* a, const uint32_t* b) {
    asm volatile(
        "mma.sync.aligned.m16n8k16.row.col.f32.f16.f16.f32 "
        "{%0,%1,%2,%3}, {%4,%5,%6,%7}, {%8,%9}, {%0,%1,%2,%3};\n"
        : "+f"(c[0]), "+f"(c[1]), "+f"(c[2]), "+f"(c[3])
        : "r"(a[0]), "r"(a[1]), "r"(a[2]), "r"(a[3]), "r"(b[0]), "r"(b[1]));
}

__global__ __launch_bounds__(NTHR, 1) void gemm_f16(const float* __restrict__ bias,
                                                    float* __restrict__ Y) {
    extern __shared__ __half sm[];
    const uint32_t s0 = (uint32_t)__cvta_generic_to_shared(sm);

    const int tid = threadIdx.x;
    const int wid = tid >> 5, lane = tid & 31;
    const int wm = wid >> 2, wn = wid & 3;       // 2x4 warps, warp tile 64x64
    const int m0 = blockIdx.y * BM, n0 = blockIdx.x * BN;

    float acc[4][8][4];
#pragma unroll
    for (int i = 0; i < 4; ++i)
#pragma unroll
        for (int j = 0; j < 8; ++j)
#pragma unroll
            for (int r = 0; r < 4; ++r) acc[i][j][r] = 0.f;

    const int t8 = lane >> 3, rr = lane & 7;
    const int a_row = (t8 & 1) * 8 + rr;
    const int a_col = (t8 >> 1) * 8;
    const int b_row = (t8 >> 1) * 8 + rr;
    const int b_col = (t8 & 1) * 8;
    const int a_base_row = wm * 64 + a_row;
    const int b_base_row = wn * 64 + b_row;

    auto load_stage = [&](int st, int kt) {
        const int k0 = kt * BK;
        const uint32_t sA = s0 + (uint32_t)st * STG;
        const uint32_t sB = sA + ABYTES;
#pragma unroll
        for (int j = 0; j < 8; ++j) {          // A: 2048 chunks -> 8/thread
            const int idx = tid + j * NTHR;
            const int row = idx >> 4, c = idx & 15;
            cp16(sA + (uint32_t)(row * SKP + c * 8) * 2u,
                 g_xh + (size_t)(m0 + row) * K_DIM + k0 + c * 8);
        }
#pragma unroll
        for (int j = 0; j < 16; ++j) {         // B: 4096 chunks -> 16/thread
            const int idx = tid + j * NTHR;
            const int row = idx >> 4, c = idx & 15;
            cp16(sB + (uint32_t)(row * SKP + c * 8) * 2u,
                 g_wh + (size_t)(n0 + row) * K_DIM + k0 + c * 8);
        }
    };

    load_stage(0, 0);
    asm volatile("cp.async.commit_group;\n");

    uint32_t afr[2][4][4], bfr[2][8][2];

    auto load_frags = [&](uint32_t sA, uint32_t sB, int ks, int buf) {
        const int kc = ks * 16;
#pragma unroll
        for (int i = 0; i < 4; ++i) {
            const uint32_t off =
                (uint32_t)((a_base_row + i * 16) * SKP + kc + a_col) * 2u;
            ldsm4(afr[buf][i], sA + off);
        }
#pragma unroll
        for (int p = 0; p < 4; ++p) {
            const uint32_t off =
                (uint32_t)((b_base_row + p * 16) * SKP + kc + b_col) * 2u;
            uint32_t u[4];
            ldsm4(u, sB + off);
            bfr[buf][2 * p][0] = u[0]; bfr[buf][2 * p][1] = u[1];
            bfr[buf][2 * p + 1][0] = u[2]; bfr[buf][2 * p + 1][1] = u[3];
        }
    };

    for (int kt = 0; kt < NKT; ++kt) {
        const int st = kt & 1;
        asm volatile("cp.async.wait_group 0;\n");
        __syncthreads();   // stage kt visible everywhere; all warps past kt-1
        if (kt + 1 < NKT) {
            load_stage(st ^ 1, kt + 1);
            asm volatile("cp.async.commit_group;\n");
        }

        const uint32_t sA = s0 + (uint32_t)st * STG;
        const uint32_t sB = sA + ABYTES;

        load_frags(sA, sB, 0, 0);
#pragma unroll
        for (int ks = 0; ks < 8; ++ks) {
            const int cur = ks & 1;
            if (ks < 7) load_frags(sA, sB, ks + 1, cur ^ 1);
#pragma unroll
            for (int i = 0; i < 4; ++i)
#pragma unroll
                for (int j = 0; j < 8; ++j)
                    hmma(acc[i][j], afr[cur][i], bfr[cur][j]);
        }
    }

    // ---- epilogue ----
    const int g = lane >> 2, t = lane & 3;
#pragma unroll
    for (int i = 0; i < 4; ++i) {
#pragma unroll
        for (int j = 0; j < 8; ++j) {
            const int row = m0 + wm * 64 + i * 16 + g;
            const int col = n0 + wn * 64 + j * 8 + t * 2;
            const float b0 = __ldg(&bias[col]);
            const float b1 = __ldg(&bias[col + 1]);
            float2 r0 = make_float2(acc[i][j][0] + b0, acc[i][j][1] + b1);
            float2 r1 = make_float2(acc[i][j][2] + b0, acc[i][j][3] + b1);
            *reinterpret_cast<float2*>(&Y[(size_t)row * N_DIM + col]) = r0;
            *reinterpret_cast<float2*>(&Y[(size_t)(row + 8) * N_DIM + col]) = r1;
        }
    }
}

// ===========================================================================
extern "C" void kernel_launch(void* const* d_in, const int* in_sizes, int n_in,
                              void* d_out, int out_size) {
    const float* x = (const float*)d_in[0];
    const float* weight = (const float*)d_in[1];
    const float* bias = (const float*)d_in[2];
    const float* centroids = (const float*)d_in[3];
    float* Y = (float*)d_out;

    quantize_w<<<NUM_VEC / 256, 256>>>(weight, centroids);
    convert_x<<<(int)(((size_t)M_DIM * K_DIM / 4) / 256), 256>>>(x);

    cudaFuncSetAttribute(gemm_f16, cudaFuncAttributeMaxDynamicSharedMemorySize, SMEM_BYTES);
    dim3 grid(N_DIM / BN, M_DIM / BM);   // (16, 128)
    gemm_f16<<<grid, NTHR, SMEM_BYTES>>>(bias, Y);
}

// round 9
// speedup vs baseline: 6.2975x; 1.0259x over previous
#include <cuda_runtime.h>
#include <cuda_fp16.h>
#include <cstdint>

#define K_DIM 4096
#define N_DIM 4096
#define M_DIM 16384
#define NUM_VEC ((N_DIM * K_DIM) / 8)

// Scratch (__device__ globals; allocation-free rule)
__device__ __half g_wh[(size_t)N_DIM * K_DIM];   // fp16 q_weight
__device__ __half g_xh[(size_t)M_DIM * K_DIM];   // fp16 x

// ===========================================================================
// Kernel 1: VPTQ quantize -> fp16 q_weight.  4 vectors/thread, div-free argmin:
//   argmin_k ||v/|v| - c_k||^2  ==  argmax_k ( dot(v,c_k) - (|v|+eps)*cc_k/2 )
// ===========================================================================
__global__ __launch_bounds__(256) void quantize_w(const float* __restrict__ weight,
                                                  const float* __restrict__ centroids) {
    __shared__ float sc[2048];    // centroids
    __shared__ float shcc[256];   // |c|^2 / 2
    __shared__ float scc[256];    // |c|^2
    const int tid = threadIdx.x;
    for (int i = tid; i < 2048; i += 256) sc[i] = centroids[i];
    __syncthreads();
    if (tid < 256) {
        float s = 0.f;
#pragma unroll
        for (int j = 0; j < 8; ++j) { float c = sc[tid * 8 + j]; s += c * c; }
        scc[tid] = s;
        shcc[tid] = 0.5f * s;
    }
    __syncthreads();

    const int vbase = blockIdx.x * 1024 + tid;   // this thread: vbase + 256*u, u=0..3

    float v[4][8];
    float nrm[4];
#pragma unroll
    for (int u = 0; u < 4; ++u) {
        const float4* p = reinterpret_cast<const float4*>(weight + (size_t)(vbase + 256 * u) * 8);
        float4 a = p[0], b = p[1];
        v[u][0] = a.x; v[u][1] = a.y; v[u][2] = a.z; v[u][3] = a.w;
        v[u][4] = b.x; v[u][5] = b.y; v[u][6] = b.z; v[u][7] = b.w;
        float vv = 0.f;
#pragma unroll
        for (int j = 0; j < 8; ++j) vv += v[u][j] * v[u][j];
        nrm[u] = __fsqrt_rn(vv) + 1e-8f;
    }

    float best[4] = {-3.402823e38f, -3.402823e38f, -3.402823e38f, -3.402823e38f};
    int bidx[4] = {0, 0, 0, 0};

    for (int k = 0; k < 256; ++k) {
        const float4 c0 = *reinterpret_cast<const float4*>(sc + k * 8);
        const float4 c1 = *reinterpret_cast<const float4*>(sc + k * 8 + 4);
        const float h = shcc[k];
#pragma unroll
        for (int u = 0; u < 4; ++u) {
            float d;
            d = v[u][0] * c0.x;
            d = fmaf(v[u][1], c0.y, d);
            d = fmaf(v[u][2], c0.z, d);
            d = fmaf(v[u][3], c0.w, d);
            d = fmaf(v[u][4], c1.x, d);
            d = fmaf(v[u][5], c1.y, d);
            d = fmaf(v[u][6], c1.z, d);
            d = fmaf(v[u][7], c1.w, d);
            const float s = fmaf(-nrm[u], h, d);
            if (s > best[u]) { best[u] = s; bidx[u] = k; }  // first-max == first-min of d2
        }
    }

#pragma unroll
    for (int u = 0; u < 4; ++u) {
        const int k = bidx[u];
        const float* cb = sc + k * 8;
        float cd = 0.f;
#pragma unroll
        for (int j = 0; j < 8; ++j) cd += v[u][j] * cb[j];
        const float scale = __fdiv_rn(cd, scc[k] + 1e-8f);
        union { __half h[8]; uint4 q; } ph;
#pragma unroll
        for (int j = 0; j < 8; ++j) ph.h[j] = __float2half_rn(cb[j] * scale);
        reinterpret_cast<uint4*>(g_wh)[vbase + 256 * u] = ph.q;
    }
}

// ===========================================================================
// Kernel 2: x -> fp16
// ===========================================================================
__global__ void convert_x(const float* __restrict__ x) {
    const size_t gid = (size_t)blockIdx.x * 256 + threadIdx.x;
    float4 v = reinterpret_cast<const float4*>(x)[gid];
    union { __half2 h2[2]; uint2 u; } p;
    p.h2[0] = __floats2half2_rn(v.x, v.y);
    p.h2[1] = __floats2half2_rn(v.z, v.w);
    reinterpret_cast<uint2*>(g_xh)[gid] = p.u;
}

// ===========================================================================
// Kernel 3: PERSISTENT fp16 GEMM  Y[M,N] = Xh @ Wh^T + bias  (fp32 accum)
// 148 CTAs; each walks tiles bx, bx+148, ... with the cp.async pipeline
// carried across tile boundaries (epilogue overlaps next tile's prefetch).
// CTA tile 128x256x128, 256 thr (8 warps 2x4, warp tile 64x64), ldmatrix
// with register double-buffering, 2 smem stages.
// ===========================================================================
#define BM 128
#define BN 256
#define BK 128
#define SKP 136                        // row stride elems (272B), LDSM conflict-free
#define NKT (K_DIM / BK)               // 32
#define ABYTES (BM * SKP * 2)          // 34816
#define BBYTES (BN * SKP * 2)          // 69632
#define STG (ABYTES + BBYTES)          // 104448
#define SMEM_BYTES (2 * STG)           // 208896
#define NTHR 256
#define NTILES ((M_DIM / BM) * (N_DIM / BN))   // 2048
#define GRID 148

__device__ __forceinline__ void cp16(uint32_t saddr, const void* g) {
    asm volatile("cp.async.cg.shared.global [%0], [%1], 16;\n" ::"r"(saddr), "l"(g));
}
__device__ __forceinline__ void ldsm4(uint32_t* r, uint32_t addr) {
    asm volatile("ldmatrix.sync.aligned.m8n8.x4.shared.b16 {%0,%1,%2,%3}, [%4];"
                 : "=r"(r[0]), "=r"(r[1]), "=r"(r[2]), "=r"(r[3]) : "r"(addr));
}
__device__ __forceinline__ void hmma(float* c, const uint32_t* a, const uint32_t* b) {
    asm volatile(
        "mma.sync.aligned.m16n8k16.row.col.f32.f16.f16.f32 "
        "{%0,%1,%2,%3}, {%4,%5,%6,%7}, {%8,%9}, {%0,%1,%2,%3};\n"
        : "+f"(c[0]), "+f"(c[1]), "+f"(c[2]), "+f"(c[3])
        : "r"(a[0]), "r"(a[1]), "r"(a[2]), "r"(a[3]), "r"(b[0]), "r"(b[1]));
}

__global__ __launch_bounds__(NTHR, 1) void gemm_f16(const float* __restrict__ bias,
                                                    float* __restrict__ Y) {
    extern __shared__ __half sm[];
    const uint32_t s0 = (uint32_t)__cvta_generic_to_shared(sm);

    const int tid = threadIdx.x;
    const int wid = tid >> 5, lane = tid & 31;
    const int wm = wid >> 2, wn = wid & 3;       // 2x4 warps, warp tile 64x64

    const int t8 = lane >> 3, rr = lane & 7;
    const int a_row = (t8 & 1) * 8 + rr;
    const int a_col = (t8 >> 1) * 8;
    const int b_row = (t8 >> 1) * 8 + rr;
    const int b_col = (t8 & 1) * 8;
    const int a_base_row = wm * 64 + a_row;
    const int b_base_row = wn * 64 + b_row;

    float acc[4][8][4];
#pragma unroll
    for (int i = 0; i < 4; ++i)
#pragma unroll
        for (int j = 0; j < 8; ++j)
#pragma unroll
            for (int r = 0; r < 4; ++r) acc[i][j][r] = 0.f;

    // tile -> coords: m_tile = tile>>4 (128 of them), n_tile = tile&15
    auto load_stage = [&](int st, int tile, int kt) {
        const int m0 = (tile >> 4) * BM;
        const int n0 = (tile & 15) * BN;
        const int k0 = kt * BK;
        const uint32_t sA = s0 + (uint32_t)st * STG;
        const uint32_t sB = sA + ABYTES;
#pragma unroll
        for (int j = 0; j < 8; ++j) {          // A: 2048 chunks -> 8/thread
            const int idx = tid + j * NTHR;
            const int row = idx >> 4, c = idx & 15;
            cp16(sA + (uint32_t)(row * SKP + c * 8) * 2u,
                 g_xh + (size_t)(m0 + row) * K_DIM + k0 + c * 8);
        }
#pragma unroll
        for (int j = 0; j < 16; ++j) {         // B: 4096 chunks -> 16/thread
            const int idx = tid + j * NTHR;
            const int row = idx >> 4, c = idx & 15;
            cp16(sB + (uint32_t)(row * SKP + c * 8) * 2u,
                 g_wh + (size_t)(n0 + row) * K_DIM + k0 + c * 8);
        }
    };

    uint32_t afr[2][4][4], bfr[2][8][2];
    auto load_frags = [&](uint32_t sA, uint32_t sB, int ks, int buf) {
        const int kc = ks * 16;
#pragma unroll
        for (int i = 0; i < 4; ++i) {
            const uint32_t off =
                (uint32_t)((a_base_row + i * 16) * SKP + kc + a_col) * 2u;
            ldsm4(afr[buf][i], sA + off);
        }
#pragma unroll
        for (int p = 0; p < 4; ++p) {
            const uint32_t off =
                (uint32_t)((b_base_row + p * 16) * SKP + kc + b_col) * 2u;
            uint32_t u[4];
            ldsm4(u, sB + off);
            bfr[buf][2 * p][0] = u[0]; bfr[buf][2 * p][1] = u[1];
            bfr[buf][2 * p + 1][0] = u[2]; bfr[buf][2 * p + 1][1] = u[3];
        }
    };

    const int first = blockIdx.x;
    if (first >= NTILES) return;

    int st = 0;
    load_stage(0, first, 0);
    asm volatile("cp.async.commit_group;\n");

    for (int tile = first; tile < NTILES; tile += GRID) {
        for (int kt = 0; kt < NKT; ++kt) {
            asm volatile("cp.async.wait_group 0;\n");
            __syncthreads();   // stage st ready; all warps done with st^1
            // prefetch next step (same tile next kt, or next tile kt 0)
            if (kt + 1 < NKT) {
                load_stage(st ^ 1, tile, kt + 1);
                asm volatile("cp.async.commit_group;\n");
            } else if (tile + GRID < NTILES) {
                load_stage(st ^ 1, tile + GRID, 0);
                asm volatile("cp.async.commit_group;\n");
            }

            const uint32_t sA = s0 + (uint32_t)st * STG;
            const uint32_t sB = sA + ABYTES;

            load_frags(sA, sB, 0, 0);
#pragma unroll
            for (int ks = 0; ks < 8; ++ks) {
                const int cur = ks & 1;
                if (ks < 7) load_frags(sA, sB, ks + 1, cur ^ 1);
#pragma unroll
                for (int i = 0; i < 4; ++i)
#pragma unroll
                    for (int j = 0; j < 8; ++j)
                        hmma(acc[i][j], afr[cur][i], bfr[cur][j]);
            }
            st ^= 1;
        }

        // ---- epilogue for this tile (overlaps next tile's stage-0 prefetch) ----
        {
            const int m0 = (tile >> 4) * BM;
            const int n0 = (tile & 15) * BN;
            const int g = lane >> 2, t = lane & 3;
#pragma unroll
            for (int i = 0; i < 4; ++i) {
#pragma unroll
                for (int j = 0; j < 8; ++j) {
                    const int row = m0 + wm * 64 + i * 16 + g;
                    const int col = n0 + wn * 64 + j * 8 + t * 2;
                    const float b0 = __ldg(&bias[col]);
                    const float b1 = __ldg(&bias[col + 1]);
                    float2 r0 = make_float2(acc[i][j][0] + b0, acc[i][j][1] + b1);
                    float2 r1 = make_float2(acc[i][j][2] + b0, acc[i][j][3] + b1);
                    *reinterpret_cast<float2*>(&Y[(size_t)row * N_DIM + col]) = r0;
                    *reinterpret_cast<float2*>(&Y[(size_t)(row + 8) * N_DIM + col]) = r1;
                    acc[i][j][0] = 0.f; acc[i][j][1] = 0.f;
                    acc[i][j][2] = 0.f; acc[i][j][3] = 0.f;
                }
            }
        }
    }
}

// ===========================================================================
extern "C" void kernel_launch(void* const* d_in, const int* in_sizes, int n_in,
                              void* d_out, int out_size) {
    const float* x = (const float*)d_in[0];
    const float* weight = (const float*)d_in[1];
    const float* bias = (const float*)d_in[2];
    const float* centroids = (const float*)d_in[3];
    float* Y = (float*)d_out;

    quantize_w<<<NUM_VEC / 1024, 256>>>(weight, centroids);
    convert_x<<<(int)(((size_t)M_DIM * K_DIM / 4) / 256), 256>>>(x);

    cudaFuncSetAttribute(gemm_f16, cudaFuncAttributeMaxDynamicSharedMemorySize, SMEM_BYTES);
    gemm_f16<<<GRID, NTHR, SMEM_BYTES>>>(bias, Y);
}

// round 10
// speedup vs baseline: 6.3175x; 1.0032x over previous
#include <cuda_runtime.h>
#include <cuda_fp16.h>
#include <cstdint>

#define K_DIM 4096
#define N_DIM 4096
#define M_DIM 16384
#define NUM_VEC ((N_DIM * K_DIM) / 8)

// Scratch (__device__ globals; allocation-free rule)
__device__ __half g_wh[(size_t)N_DIM * K_DIM];   // fp16 q_weight
__device__ __half g_xh[(size_t)M_DIM * K_DIM];   // fp16 x

// ===========================================================================
// Kernel 1: VPTQ quantize -> fp16 q_weight.
// 4 vectors/thread; normalized-vector scoring (reference-like rounding);
// inner product via packed fma.rn.f32x2 (2 FMAs/instr):
//   score_k = dot(n, c_k) - cc_k/2   (argmax == argmin ||n - c_k||^2)
// acc2 initialized to (-cc_k/2, 0); 4 FFMA2; score = lo + hi.
// ===========================================================================
typedef unsigned long long u64;
#define FFMA2(d, a, b, c) \
    asm("fma.rn.f32x2 %0, %1, %2, %3;" : "=l"(d) : "l"(a), "l"(b), "l"(c))

union F2U { float2 f; u64 u; };

__global__ __launch_bounds__(256) void quantize_w(const float* __restrict__ weight,
                                                  const float* __restrict__ centroids) {
    __shared__ float sc[2048];    // centroids
    __shared__ float scc[256];    // |c|^2
    __shared__ float shcc[256];   // |c|^2 / 2
    const int tid = threadIdx.x;
    for (int i = tid; i < 2048; i += 256) sc[i] = centroids[i];
    __syncthreads();
    if (tid < 256) {
        float s = 0.f;
#pragma unroll
        for (int j = 0; j < 8; ++j) { float c = sc[tid * 8 + j]; s += c * c; }
        scc[tid] = s;
        shcc[tid] = 0.5f * s;
    }
    __syncthreads();

    const int vbase = blockIdx.x * 1024 + tid;   // vectors vbase + 256*u, u=0..3

    float v[4][8];
    u64 np[4][4];                // normalized vectors packed as f32x2 pairs
#pragma unroll
    for (int u = 0; u < 4; ++u) {
        const float4* p = reinterpret_cast<const float4*>(weight + (size_t)(vbase + 256 * u) * 8);
        float4 a = p[0], b = p[1];
        v[u][0] = a.x; v[u][1] = a.y; v[u][2] = a.z; v[u][3] = a.w;
        v[u][4] = b.x; v[u][5] = b.y; v[u][6] = b.z; v[u][7] = b.w;
        float vv = 0.f;
#pragma unroll
        for (int j = 0; j < 8; ++j) vv += v[u][j] * v[u][j];
        const float norm = __fsqrt_rn(vv) + 1e-8f;
#pragma unroll
        for (int j = 0; j < 4; ++j) {
            F2U t;
            t.f.x = __fdiv_rn(v[u][2 * j], norm);      // per-element normalize,
            t.f.y = __fdiv_rn(v[u][2 * j + 1], norm);  // matches reference form
            np[u][j] = t.u;
        }
    }

    float best[4] = {-3.402823e38f, -3.402823e38f, -3.402823e38f, -3.402823e38f};
    int bidx[4] = {0, 0, 0, 0};

#pragma unroll 4
    for (int k = 0; k < 256; ++k) {
        const u64* cp = reinterpret_cast<const u64*>(sc + k * 8);   // 4 packed pairs
        const u64 c0 = cp[0], c1 = cp[1], c2 = cp[2], c3 = cp[3];
        F2U init; init.f.x = -shcc[k]; init.f.y = 0.f;
        const u64 iu = init.u;
#pragma unroll
        for (int u = 0; u < 4; ++u) {
            u64 acc;
            FFMA2(acc, np[u][0], c0, iu);
            FFMA2(acc, np[u][1], c1, acc);
            FFMA2(acc, np[u][2], c2, acc);
            FFMA2(acc, np[u][3], c3, acc);
            F2U r; r.u = acc;
            const float s = r.f.x + r.f.y;   // dot(n,c) - cc/2
            if (s > best[u]) { best[u] = s; bidx[u] = k; }
        }
    }

#pragma unroll
    for (int u = 0; u < 4; ++u) {
        const int k = bidx[u];
        const float* cb = sc + k * 8;
        float cd = 0.f;
#pragma unroll
        for (int j = 0; j < 8; ++j) cd += v[u][j] * cb[j];
        const float scale = __fdiv_rn(cd, scc[k] + 1e-8f);
        union { __half h[8]; uint4 q; } ph;
#pragma unroll
        for (int j = 0; j < 8; ++j) ph.h[j] = __float2half_rn(cb[j] * scale);
        reinterpret_cast<uint4*>(g_wh)[vbase + 256 * u] = ph.q;
    }
}

// ===========================================================================
// Kernel 2: x -> fp16
// ===========================================================================
__global__ void convert_x(const float* __restrict__ x) {
    const size_t gid = (size_t)blockIdx.x * 256 + threadIdx.x;
    float4 v = reinterpret_cast<const float4*>(x)[gid];
    union { __half2 h2[2]; uint2 u; } p;
    p.h2[0] = __floats2half2_rn(v.x, v.y);
    p.h2[1] = __floats2half2_rn(v.z, v.w);
    reinterpret_cast<uint2*>(g_xh)[gid] = p.u;
}

// ===========================================================================
// Kernel 3: PERSISTENT fp16 GEMM  Y[M,N] = Xh @ Wh^T + bias  (fp32 accum)
// (unchanged from round 9)
// ===========================================================================
#define BM 128
#define BN 256
#define BK 128
#define SKP 136
#define NKT (K_DIM / BK)
#define ABYTES (BM * SKP * 2)
#define BBYTES (BN * SKP * 2)
#define STG (ABYTES + BBYTES)
#define SMEM_BYTES (2 * STG)
#define NTHR 256
#define NTILES ((M_DIM / BM) * (N_DIM / BN))
#define GRID 148

__device__ __forceinline__ void cp16(uint32_t saddr, const void* g) {
    asm volatile("cp.async.cg.shared.global [%0], [%1], 16;\n" ::"r"(saddr), "l"(g));
}
__device__ __forceinline__ void ldsm4(uint32_t* r, uint32_t addr) {
    asm volatile("ldmatrix.sync.aligned.m8n8.x4.shared.b16 {%0,%1,%2,%3}, [%4];"
                 : "=r"(r[0]), "=r"(r[1]), "=r"(r[2]), "=r"(r[3]) : "r"(addr));
}
__device__ __forceinline__ void hmma(float* c, const uint32_t* a, const uint32_t* b) {
    asm volatile(
        "mma.sync.aligned.m16n8k16.row.col.f32.f16.f16.f32 "
        "{%0,%1,%2,%3}, {%4,%5,%6,%7}, {%8,%9}, {%0,%1,%2,%3};\n"
        : "+f"(c[0]), "+f"(c[1]), "+f"(c[2]), "+f"(c[3])
        : "r"(a[0]), "r"(a[1]), "r"(a[2]), "r"(a[3]), "r"(b[0]), "r"(b[1]));
}

__global__ __launch_bounds__(NTHR, 1) void gemm_f16(const float* __restrict__ bias,
                                                    float* __restrict__ Y) {
    extern __shared__ __half sm[];
    const uint32_t s0 = (uint32_t)__cvta_generic_to_shared(sm);

    const int tid = threadIdx.x;
    const int wid = tid >> 5, lane = tid & 31;
    const int wm = wid >> 2, wn = wid & 3;

    const int t8 = lane >> 3, rr = lane & 7;
    const int a_row = (t8 & 1) * 8 + rr;
    const int a_col = (t8 >> 1) * 8;
    const int b_row = (t8 >> 1) * 8 + rr;
    const int b_col = (t8 & 1) * 8;
    const int a_base_row = wm * 64 + a_row;
    const int b_base_row = wn * 64 + b_row;

    float acc[4][8][4];
#pragma unroll
    for (int i = 0; i < 4; ++i)
#pragma unroll
        for (int j = 0; j < 8; ++j)
#pragma unroll
            for (int r = 0; r < 4; ++r) acc[i][j][r] = 0.f;

    auto load_stage = [&](int st, int tile, int kt) {
        const int m0 = (tile >> 4) * BM;
        const int n0 = (tile & 15) * BN;
        const int k0 = kt * BK;
        const uint32_t sA = s0 + (uint32_t)st * STG;
        const uint32_t sB = sA + ABYTES;
#pragma unroll
        for (int j = 0; j < 8; ++j) {
            const int idx = tid + j * NTHR;
            const int row = idx >> 4, c = idx & 15;
            cp16(sA + (uint32_t)(row * SKP + c * 8) * 2u,
                 g_xh + (size_t)(m0 + row) * K_DIM + k0 + c * 8);
        }
#pragma unroll
        for (int j = 0; j < 16; ++j) {
            const int idx = tid + j * NTHR;
            const int row = idx >> 4, c = idx & 15;
            cp16(sB + (uint32_t)(row * SKP + c * 8) * 2u,
                 g_wh + (size_t)(n0 + row) * K_DIM + k0 + c * 8);
        }
    };

    uint32_t afr[2][4][4], bfr[2][8][2];
    auto load_frags = [&](uint32_t sA, uint32_t sB, int ks, int buf) {
        const int kc = ks * 16;
#pragma unroll
        for (int i = 0; i < 4; ++i) {
            const uint32_t off =
                (uint32_t)((a_base_row + i * 16) * SKP + kc + a_col) * 2u;
            ldsm4(afr[buf][i], sA + off);
        }
#pragma unroll
        for (int p = 0; p < 4; ++p) {
            const uint32_t off =
                (uint32_t)((b_base_row + p * 16) * SKP + kc + b_col) * 2u;
            uint32_t u[4];
            ldsm4(u, sB + off);
            bfr[buf][2 * p][0] = u[0]; bfr[buf][2 * p][1] = u[1];
            bfr[buf][2 * p + 1][0] = u[2]; bfr[buf][2 * p + 1][1] = u[3];
        }
    };

    const int first = blockIdx.x;
    if (first >= NTILES) return;

    int st = 0;
    load_stage(0, first, 0);
    asm volatile("cp.async.commit_group;\n");

    for (int tile = first; tile < NTILES; tile += GRID) {
        for (int kt = 0; kt < NKT; ++kt) {
            asm volatile("cp.async.wait_group 0;\n");
            __syncthreads();
            if (kt + 1 < NKT) {
                load_stage(st ^ 1, tile, kt + 1);
                asm volatile("cp.async.commit_group;\n");
            } else if (tile + GRID < NTILES) {
                load_stage(st ^ 1, tile + GRID, 0);
                asm volatile("cp.async.commit_group;\n");
            }

            const uint32_t sA = s0 + (uint32_t)st * STG;
            const uint32_t sB = sA + ABYTES;

            load_frags(sA, sB, 0, 0);
#pragma unroll
            for (int ks = 0; ks < 8; ++ks) {
                const int cur = ks & 1;
                if (ks < 7) load_frags(sA, sB, ks + 1, cur ^ 1);
#pragma unroll
                for (int i = 0; i < 4; ++i)
#pragma unroll
                    for (int j = 0; j < 8; ++j)
                        hmma(acc[i][j], afr[cur][i], bfr[cur][j]);
            }
            st ^= 1;
        }

        {
            const int m0 = (tile >> 4) * BM;
            const int n0 = (tile & 15) * BN;
            const int g = lane >> 2, t = lane & 3;
#pragma unroll
            for (int i = 0; i < 4; ++i) {
#pragma unroll
                for (int j = 0; j < 8; ++j) {
                    const int row = m0 + wm * 64 + i * 16 + g;
                    const int col = n0 + wn * 64 + j * 8 + t * 2;
                    const float b0 = __ldg(&bias[col]);
                    const float b1 = __ldg(&bias[col + 1]);
                    float2 r0 = make_float2(acc[i][j][0] + b0, acc[i][j][1] + b1);
                    float2 r1 = make_float2(acc[i][j][2] + b0, acc[i][j][3] + b1);
                    *reinterpret_cast<float2*>(&Y[(size_t)row * N_DIM + col]) = r0;
                    *reinterpret_cast<float2*>(&Y[(size_t)(row + 8) * N_DIM + col]) = r1;
                    acc[i][j][0] = 0.f; acc[i][j][1] = 0.f;
                    acc[i][j][2] = 0.f; acc[i][j][3] = 0.f;
                }
            }
        }
    }
}

// ===========================================================================
extern "C" void kernel_launch(void* const* d_in, const int* in_sizes, int n_in,
                              void* d_out, int out_size) {
    const float* x = (const float*)d_in[0];
    const float* weight = (const float*)d_in[1];
    const float* bias = (const float*)d_in[2];
    const float* centroids = (const float*)d_in[3];
    float* Y = (float*)d_out;

    quantize_w<<<NUM_VEC / 1024, 256>>>(weight, centroids);
    convert_x<<<(int)(((size_t)M_DIM * K_DIM / 4) / 256), 256>>>(x);

    cudaFuncSetAttribute(gemm_f16, cudaFuncAttributeMaxDynamicSharedMemorySize, SMEM_BYTES);
    gemm_f16<<<GRID, NTHR, SMEM_BYTES>>>(bias, Y);
}

// round 11
// speedup vs baseline: 6.3465x; 1.0046x over previous
#include <cuda_runtime.h>
#include <cuda_fp16.h>
#include <cstdint>

#define K_DIM 4096
#define N_DIM 4096
#define M_DIM 16384
#define NUM_VEC ((N_DIM * K_DIM) / 8)

// Scratch (__device__ globals; allocation-free rule)
__device__ __half g_wh[(size_t)N_DIM * K_DIM];   // fp16 q_weight
__device__ __half g_xh[(size_t)M_DIM * K_DIM];   // fp16 x

// ===========================================================================
// Kernel 1 (fused prologue):
//   blocks [0, QBLK):            VPTQ quantize weight -> fp16 (compute-bound)
//   blocks [QBLK, QBLK+CBLK):    x fp32 -> fp16        (bandwidth-bound)
// The converter's DRAM traffic hides under the quantizer's FMA work.
// ===========================================================================
typedef unsigned long long u64;
#define FFMA2(d, a, b, c) \
    asm("fma.rn.f32x2 %0, %1, %2, %3;" : "=l"(d) : "l"(a), "l"(b), "l"(c))
union F2U { float2 f; u64 u; };

#define QBLK (NUM_VEC / 1024)                    // 2048
#define CBLK ((M_DIM * (K_DIM / 4)) / 1024)      // 16384  (x as float4, 1024/block)

__global__ __launch_bounds__(256) void prologue(const float* __restrict__ weight,
                                                const float* __restrict__ centroids,
                                                const float* __restrict__ x) {
    const int tid = threadIdx.x;

    if (blockIdx.x >= QBLK) {
        // ---------------- convert_x part: 1024 float4 per block ----------------
        const size_t base = (size_t)(blockIdx.x - QBLK) * 1024 + tid;
#pragma unroll
        for (int j = 0; j < 4; ++j) {
            const size_t gid = base + (size_t)j * 256;
            float4 v = reinterpret_cast<const float4*>(x)[gid];
            union { __half2 h2[2]; uint2 u; } p;
            p.h2[0] = __floats2half2_rn(v.x, v.y);
            p.h2[1] = __floats2half2_rn(v.z, v.w);
            reinterpret_cast<uint2*>(g_xh)[gid] = p.u;
        }
        return;
    }

    // ---------------- quantize part ----------------
    __shared__ float sc[2048];    // centroids
    __shared__ float scc[256];    // |c|^2
    __shared__ float shcc[256];   // |c|^2 / 2
    for (int i = tid; i < 2048; i += 256) sc[i] = centroids[i];
    __syncthreads();
    if (tid < 256) {
        float s = 0.f;
#pragma unroll
        for (int j = 0; j < 8; ++j) { float c = sc[tid * 8 + j]; s += c * c; }
        scc[tid] = s;
        shcc[tid] = 0.5f * s;
    }
    __syncthreads();

    const int vbase = blockIdx.x * 1024 + tid;   // vectors vbase + 256*u, u=0..3

    // Build normalized packed vectors; do NOT keep raw v live (reload later).
    u64 np[4][4];
#pragma unroll
    for (int u = 0; u < 4; ++u) {
        const float4* p = reinterpret_cast<const float4*>(weight + (size_t)(vbase + 256 * u) * 8);
        float4 a = p[0], b = p[1];
        float w[8] = {a.x, a.y, a.z, a.w, b.x, b.y, b.z, b.w};
        float vv = 0.f;
#pragma unroll
        for (int j = 0; j < 8; ++j) vv += w[j] * w[j];
        const float norm = __fsqrt_rn(vv) + 1e-8f;
#pragma unroll
        for (int j = 0; j < 4; ++j) {
            F2U t;
            t.f.x = __fdiv_rn(w[2 * j], norm);
            t.f.y = __fdiv_rn(w[2 * j + 1], norm);
            np[u][j] = t.u;
        }
    }

    float best[4] = {-3.402823e38f, -3.402823e38f, -3.402823e38f, -3.402823e38f};
    int bidx[4] = {0, 0, 0, 0};

#pragma unroll 4
    for (int k = 0; k < 256; ++k) {
        const u64* cp = reinterpret_cast<const u64*>(sc + k * 8);
        const u64 c0 = cp[0], c1 = cp[1], c2 = cp[2], c3 = cp[3];
        F2U init; init.f.x = -shcc[k]; init.f.y = 0.f;
        const u64 iu = init.u;
#pragma unroll
        for (int u = 0; u < 4; ++u) {
            u64 acc;
            FFMA2(acc, np[u][0], c0, iu);
            FFMA2(acc, np[u][1], c1, acc);
            FFMA2(acc, np[u][2], c2, acc);
            FFMA2(acc, np[u][3], c3, acc);
            F2U r; r.u = acc;
            const float s = r.f.x + r.f.y;   // dot(n,c) - cc/2
            if (s > best[u]) { best[u] = s; bidx[u] = k; }
        }
    }

    // Reload original vectors (L2 hit; DRAM idle) and emit fp16 q_weight.
#pragma unroll
    for (int u = 0; u < 4; ++u) {
        const int k = bidx[u];
        const float* cb = sc + k * 8;
        const float4* p = reinterpret_cast<const float4*>(weight + (size_t)(vbase + 256 * u) * 8);
        float4 a = p[0], b = p[1];
        const float w[8] = {a.x, a.y, a.z, a.w, b.x, b.y, b.z, b.w};
        float cd = 0.f;
#pragma unroll
        for (int j = 0; j < 8; ++j) cd += w[j] * cb[j];
        const float scale = __fdiv_rn(cd, scc[k] + 1e-8f);
        union { __half h[8]; uint4 q; } ph;
#pragma unroll
        for (int j = 0; j < 8; ++j) ph.h[j] = __float2half_rn(cb[j] * scale);
        reinterpret_cast<uint4*>(g_wh)[vbase + 256 * u] = ph.q;
    }
}

// ===========================================================================
// Kernel 2: PERSISTENT fp16 GEMM  Y[M,N] = Xh @ Wh^T + bias  (fp32 accum)
// (unchanged — parked at the legacy-HMMA plateau)
// ===========================================================================
#define BM 128
#define BN 256
#define BK 128
#define SKP 136
#define NKT (K_DIM / BK)
#define ABYTES (BM * SKP * 2)
#define BBYTES (BN * SKP * 2)
#define STG (ABYTES + BBYTES)
#define SMEM_BYTES (2 * STG)
#define NTHR 256
#define NTILES ((M_DIM / BM) * (N_DIM / BN))
#define GRID 148

__device__ __forceinline__ void cp16(uint32_t saddr, const void* g) {
    asm volatile("cp.async.cg.shared.global [%0], [%1], 16;\n" ::"r"(saddr), "l"(g));
}
__device__ __forceinline__ void ldsm4(uint32_t* r, uint32_t addr) {
    asm volatile("ldmatrix.sync.aligned.m8n8.x4.shared.b16 {%0,%1,%2,%3}, [%4];"
                 : "=r"(r[0]), "=r"(r[1]), "=r"(r[2]), "=r"(r[3]) : "r"(addr));
}
__device__ __forceinline__ void hmma(float* c, const uint32_t* a, const uint32_t* b) {
    asm volatile(
        "mma.sync.aligned.m16n8k16.row.col.f32.f16.f16.f32 "
        "{%0,%1,%2,%3}, {%4,%5,%6,%7}, {%8,%9}, {%0,%1,%2,%3};\n"
        : "+f"(c[0]), "+f"(c[1]), "+f"(c[2]), "+f"(c[3])
        : "r"(a[0]), "r"(a[1]), "r"(a[2]), "r"(a[3]), "r"(b[0]), "r"(b[1]));
}

__global__ __launch_bounds__(NTHR, 1) void gemm_f16(const float* __restrict__ bias,
                                                    float* __restrict__ Y) {
    extern __shared__ __half sm[];
    const uint32_t s0 = (uint32_t)__cvta_generic_to_shared(sm);

    const int tid = threadIdx.x;
    const int wid = tid >> 5, lane = tid & 31;
    const int wm = wid >> 2, wn = wid & 3;

    const int t8 = lane >> 3, rr = lane & 7;
    const int a_row = (t8 & 1) * 8 + rr;
    const int a_col = (t8 >> 1) * 8;
    const int b_row = (t8 >> 1) * 8 + rr;
    const int b_col = (t8 & 1) * 8;
    const int a_base_row = wm * 64 + a_row;
    const int b_base_row = wn * 64 + b_row;

    float acc[4][8][4];
#pragma unroll
    for (int i = 0; i < 4; ++i)
#pragma unroll
        for (int j = 0; j < 8; ++j)
#pragma unroll
            for (int r = 0; r < 4; ++r) acc[i][j][r] = 0.f;

    auto load_stage = [&](int st, int tile, int kt) {
        const int m0 = (tile >> 4) * BM;
        const int n0 = (tile & 15) * BN;
        const int k0 = kt * BK;
        const uint32_t sA = s0 + (uint32_t)st * STG;
        const uint32_t sB = sA + ABYTES;
#pragma unroll
        for (int j = 0; j < 8; ++j) {
            const int idx = tid + j * NTHR;
            const int row = idx >> 4, c = idx & 15;
            cp16(sA + (uint32_t)(row * SKP + c * 8) * 2u,
                 g_xh + (size_t)(m0 + row) * K_DIM + k0 + c * 8);
        }
#pragma unroll
        for (int j = 0; j < 16; ++j) {
            const int idx = tid + j * NTHR;
            const int row = idx >> 4, c = idx & 15;
            cp16(sB + (uint32_t)(row * SKP + c * 8) * 2u,
                 g_wh + (size_t)(n0 + row) * K_DIM + k0 + c * 8);
        }
    };

    uint32_t afr[2][4][4], bfr[2][8][2];
    auto load_frags = [&](uint32_t sA, uint32_t sB, int ks, int buf) {
        const int kc = ks * 16;
#pragma unroll
        for (int i = 0; i < 4; ++i) {
            const uint32_t off =
                (uint32_t)((a_base_row + i * 16) * SKP + kc + a_col) * 2u;
            ldsm4(afr[buf][i], sA + off);
        }
#pragma unroll
        for (int p = 0; p < 4; ++p) {
            const uint32_t off =
                (uint32_t)((b_base_row + p * 16) * SKP + kc + b_col) * 2u;
            uint32_t u[4];
            ldsm4(u, sB + off);
            bfr[buf][2 * p][0] = u[0]; bfr[buf][2 * p][1] = u[1];
            bfr[buf][2 * p + 1][0] = u[2]; bfr[buf][2 * p + 1][1] = u[3];
        }
    };

    const int first = blockIdx.x;
    if (first >= NTILES) return;

    int st = 0;
    load_stage(0, first, 0);
    asm volatile("cp.async.commit_group;\n");

    for (int tile = first; tile < NTILES; tile += GRID) {
        for (int kt = 0; kt < NKT; ++kt) {
            asm volatile("cp.async.wait_group 0;\n");
            __syncthreads();
            if (kt + 1 < NKT) {
                load_stage(st ^ 1, tile, kt + 1);
                asm volatile("cp.async.commit_group;\n");
            } else if (tile + GRID < NTILES) {
                load_stage(st ^ 1, tile + GRID, 0);
                asm volatile("cp.async.commit_group;\n");
            }

            const uint32_t sA = s0 + (uint32_t)st * STG;
            const uint32_t sB = sA + ABYTES;

            load_frags(sA, sB, 0, 0);
#pragma unroll
            for (int ks = 0; ks < 8; ++ks) {
                const int cur = ks & 1;
                if (ks < 7) load_frags(sA, sB, ks + 1, cur ^ 1);
#pragma unroll
                for (int i = 0; i < 4; ++i)
#pragma unroll
                    for (int j = 0; j < 8; ++j)
                        hmma(acc[i][j], afr[cur][i], bfr[cur][j]);
            }
            st ^= 1;
        }

        {
            const int m0 = (tile >> 4) * BM;
            const int n0 = (tile & 15) * BN;
            const int g = lane >> 2, t = lane & 3;
#pragma unroll
            for (int i = 0; i < 4; ++i) {
#pragma unroll
                for (int j = 0; j < 8; ++j) {
                    const int row = m0 + wm * 64 + i * 16 + g;
                    const int col = n0 + wn * 64 + j * 8 + t * 2;
                    const float b0 = __ldg(&bias[col]);
                    const float b1 = __ldg(&bias[col + 1]);
                    float2 r0 = make_float2(acc[i][j][0] + b0, acc[i][j][1] + b1);
                    float2 r1 = make_float2(acc[i][j][2] + b0, acc[i][j][3] + b1);
                    *reinterpret_cast<float2*>(&Y[(size_t)row * N_DIM + col]) = r0;
                    *reinterpret_cast<float2*>(&Y[(size_t)(row + 8) * N_DIM + col]) = r1;
                    acc[i][j][0] = 0.f; acc[i][j][1] = 0.f;
                    acc[i][j][2] = 0.f; acc[i][j][3] = 0.f;
                }
            }
        }
    }
}

// ===========================================================================
extern "C" void kernel_launch(void* const* d_in, const int* in_sizes, int n_in,
                              void* d_out, int out_size) {
    const float* x = (const float*)d_in[0];
    const float* weight = (const float*)d_in[1];
    const float* bias = (const float*)d_in[2];
    const float* centroids = (const float*)d_in[3];
    float* Y = (float*)d_out;

    prologue<<<QBLK + CBLK, 256>>>(weight, centroids, x);

    cudaFuncSetAttribute(gemm_f16, cudaFuncAttributeMaxDynamicSharedMemorySize, SMEM_BYTES);
    gemm_f16<<<GRID, NTHR, SMEM_BYTES>>>(bias, Y);
}

// round 12
// speedup vs baseline: 6.4216x; 1.0118x over previous
#include <cuda_runtime.h>
#include <cuda_fp16.h>
#include <cstdint>

#define K_DIM 4096
#define N_DIM 4096
#define M_DIM 16384
#define NUM_VEC ((N_DIM * K_DIM) / 8)

__device__ __half g_wh[(size_t)N_DIM * K_DIM];   // fp16 q_weight
__device__ __half g_xh[(size_t)M_DIM * K_DIM];   // fp16 x

// ===========================================================================
// Kernel 1 (fused prologue):
//   blocks [0, QBLK):         VPTQ quantize weight -> fp16 (2 vec/thread)
//   blocks [QBLK, QBLK+CBLK): x fp32 -> fp16 (bandwidth-bound, backfills)
// ===========================================================================
typedef unsigned long long u64;
#define FFMA2(d, a, b, c) \
    asm("fma.rn.f32x2 %0, %1, %2, %3;" : "=l"(d) : "l"(a), "l"(b), "l"(c))
union F2U { float2 f; u64 u; };

#define QBLK (NUM_VEC / 512)                     // 4096 (512 vectors/block)
#define CBLK ((M_DIM * (K_DIM / 4)) / 1024)      // 16384

__global__ __launch_bounds__(256) void prologue(const float* __restrict__ weight,
                                                const float* __restrict__ centroids,
                                                const float* __restrict__ x) {
    const int tid = threadIdx.x;

    if (blockIdx.x >= QBLK) {
        // ---- convert_x: 1024 float4 per block ----
        const size_t base = (size_t)(blockIdx.x - QBLK) * 1024 + tid;
#pragma unroll
        for (int j = 0; j < 4; ++j) {
            const size_t gid = base + (size_t)j * 256;
            float4 v = reinterpret_cast<const float4*>(x)[gid];
            union { __half2 h2[2]; uint2 u; } p;
            p.h2[0] = __floats2half2_rn(v.x, v.y);
            p.h2[1] = __floats2half2_rn(v.z, v.w);
            reinterpret_cast<uint2*>(g_xh)[gid] = p.u;
        }
        return;
    }

    // ---- quantize: 2 vectors/thread ----
    __shared__ float sc[2048];
    __shared__ float scc[256];
    __shared__ float shcc[256];
    for (int i = tid; i < 2048; i += 256) sc[i] = centroids[i];
    __syncthreads();
    if (tid < 256) {
        float s = 0.f;
#pragma unroll
        for (int j = 0; j < 8; ++j) { float c = sc[tid * 8 + j]; s += c * c; }
        scc[tid] = s;
        shcc[tid] = 0.5f * s;
    }
    __syncthreads();

    const int vbase = blockIdx.x * 512 + tid;    // vectors vbase, vbase+256

    u64 np[2][4];
#pragma unroll
    for (int u = 0; u < 2; ++u) {
        const float4* p = reinterpret_cast<const float4*>(weight + (size_t)(vbase + 256 * u) * 8);
        float4 a = p[0], b = p[1];
        float w[8] = {a.x, a.y, a.z, a.w, b.x, b.y, b.z, b.w};
        float vv = 0.f;
#pragma unroll
        for (int j = 0; j < 8; ++j) vv += w[j] * w[j];
        const float norm = __fsqrt_rn(vv) + 1e-8f;
#pragma unroll
        for (int j = 0; j < 4; ++j) {
            F2U t;
            t.f.x = __fdiv_rn(w[2 * j], norm);
            t.f.y = __fdiv_rn(w[2 * j + 1], norm);
            np[u][j] = t.u;
        }
    }

    float best[2] = {-3.402823e38f, -3.402823e38f};
    int bidx[2] = {0, 0};

#pragma unroll 4
    for (int k = 0; k < 256; ++k) {
        const u64* cp = reinterpret_cast<const u64*>(sc + k * 8);
        const u64 c0 = cp[0], c1 = cp[1], c2 = cp[2], c3 = cp[3];
        F2U init; init.f.x = -shcc[k]; init.f.y = 0.f;
        const u64 iu = init.u;
#pragma unroll
        for (int u = 0; u < 2; ++u) {
            u64 acc;
            FFMA2(acc, np[u][0], c0, iu);
            FFMA2(acc, np[u][1], c1, acc);
            FFMA2(acc, np[u][2], c2, acc);
            FFMA2(acc, np[u][3], c3, acc);
            F2U r; r.u = acc;
            const float s = r.f.x + r.f.y;
            if (s > best[u]) { best[u] = s; bidx[u] = k; }
        }
    }

#pragma unroll
    for (int u = 0; u < 2; ++u) {
        const int k = bidx[u];
        const float* cb = sc + k * 8;
        const float4* p = reinterpret_cast<const float4*>(weight + (size_t)(vbase + 256 * u) * 8);
        float4 a = p[0], b = p[1];
        const float w[8] = {a.x, a.y, a.z, a.w, b.x, b.y, b.z, b.w};
        float cd = 0.f;
#pragma unroll
        for (int j = 0; j < 8; ++j) cd += w[j] * cb[j];
        const float scale = __fdiv_rn(cd, scc[k] + 1e-8f);
        union { __half h[8]; uint4 q; } ph;
#pragma unroll
        for (int j = 0; j < 8; ++j) ph.h[j] = __float2half_rn(cb[j] * scale);
        reinterpret_cast<uint4*>(g_wh)[vbase + 256 * u] = ph.q;
    }
}

// ===========================================================================
// Kernel 2: PERSISTENT fp16 GEMM, 2 CTAs/SM.
// CTA tile 128x128x64, 2 smem stages (73.7KB), 256 thr (8 warps 2x4,
// warp tile 64x32), single-buffered ldmatrix frags, <=128 regs.
// Two co-resident CTAs have independent barriers -> tensor pipe stays fed
// while one CTA sits in sync/LDSM fill.
// ===========================================================================
#define BM 128
#define BN 128
#define BK 64
#define SKP 72                          // 144B row stride, LDSM conflict-free
#define NKT (K_DIM / BK)                // 64
#define ABYTES (BM * SKP * 2)           // 18432
#define BBYTES (BN * SKP * 2)           // 18432
#define STG (ABYTES + BBYTES)           // 36864
#define SMEM_BYTES (2 * STG)            // 73728
#define NTHR 256
#define NTILES ((M_DIM / BM) * (N_DIM / BN))   // 4096
#define GRID 296

__device__ __forceinline__ void cp16(uint32_t saddr, const void* g) {
    asm volatile("cp.async.cg.shared.global [%0], [%1], 16;\n" ::"r"(saddr), "l"(g));
}
__device__ __forceinline__ void ldsm4(uint32_t* r, uint32_t addr) {
    asm volatile("ldmatrix.sync.aligned.m8n8.x4.shared.b16 {%0,%1,%2,%3}, [%4];"
                 : "=r"(r[0]), "=r"(r[1]), "=r"(r[2]), "=r"(r[3]) : "r"(addr));
}
__device__ __forceinline__ void hmma(float* c, const uint32_t* a, const uint32_t* b) {
    asm volatile(
        "mma.sync.aligned.m16n8k16.row.col.f32.f16.f16.f32 "
        "{%0,%1,%2,%3}, {%4,%5,%6,%7}, {%8,%9}, {%0,%1,%2,%3};\n"
        : "+f"(c[0]), "+f"(c[1]), "+f"(c[2]), "+f"(c[3])
        : "r"(a[0]), "r"(a[1]), "r"(a[2]), "r"(a[3]), "r"(b[0]), "r"(b[1]));
}

__global__ __launch_bounds__(NTHR, 2) void gemm_f16(const float* __restrict__ bias,
                                                    float* __restrict__ Y) {
    extern __shared__ __half sm[];
    const uint32_t s0 = (uint32_t)__cvta_generic_to_shared(sm);

    const int tid = threadIdx.x;
    const int wid = tid >> 5, lane = tid & 31;
    const int wm = wid >> 2, wn = wid & 3;       // 2x4 warps, warp tile 64x32

    const int t8 = lane >> 3, rr = lane & 7;
    const int a_row = (t8 & 1) * 8 + rr;
    const int a_col = (t8 >> 1) * 8;
    const int b_row = (t8 >> 1) * 8 + rr;
    const int b_col = (t8 & 1) * 8;
    const int a_base_row = wm * 64 + a_row;
    const int b_base_row = wn * 32 + b_row;

    float acc[4][4][4];
#pragma unroll
    for (int i = 0; i < 4; ++i)
#pragma unroll
        for (int j = 0; j < 4; ++j)
#pragma unroll
            for (int r = 0; r < 4; ++r) acc[i][j][r] = 0.f;

    // tile -> coords: m_tile = tile>>5 (128), n_tile = tile&31 (32)
    auto load_stage = [&](int st, int tile, int kt) {
        const int m0 = (tile >> 5) * BM;
        const int n0 = (tile & 31) * BN;
        const int k0 = kt * BK;
        const uint32_t sA = s0 + (uint32_t)st * STG;
        const uint32_t sB = sA + ABYTES;
#pragma unroll
        for (int j = 0; j < 4; ++j) {          // A: 1024 chunks -> 4/thread
            const int idx = tid + j * NTHR;
            const int row = idx >> 3, c = idx & 7;
            cp16(sA + (uint32_t)(row * SKP + c * 8) * 2u,
                 g_xh + (size_t)(m0 + row) * K_DIM + k0 + c * 8);
        }
#pragma unroll
        for (int j = 0; j < 4; ++j) {          // B: 1024 chunks -> 4/thread
            const int idx = tid + j * NTHR;
            const int row = idx >> 3, c = idx & 7;
            cp16(sB + (uint32_t)(row * SKP + c * 8) * 2u,
                 g_wh + (size_t)(n0 + row) * K_DIM + k0 + c * 8);
        }
    };

    const int first = blockIdx.x;
    if (first >= NTILES) return;

    int st = 0;
    load_stage(0, first, 0);
    asm volatile("cp.async.commit_group;\n");

    for (int tile = first; tile < NTILES; tile += GRID) {
        for (int kt = 0; kt < NKT; ++kt) {
            asm volatile("cp.async.wait_group 0;\n");
            __syncthreads();   // stage st ready; all warps done with st^1
            if (kt + 1 < NKT) {
                load_stage(st ^ 1, tile, kt + 1);
                asm volatile("cp.async.commit_group;\n");
            } else if (tile + GRID < NTILES) {
                load_stage(st ^ 1, tile + GRID, 0);
                asm volatile("cp.async.commit_group;\n");
            }

            const uint32_t sA = s0 + (uint32_t)st * STG;
            const uint32_t sB = sA + ABYTES;

#pragma unroll
            for (int ks = 0; ks < 4; ++ks) {
                const int kc = ks * 16;
                uint32_t a[4][4], b[4][2];
#pragma unroll
                for (int i = 0; i < 4; ++i) {
                    const uint32_t off =
                        (uint32_t)((a_base_row + i * 16) * SKP + kc + a_col) * 2u;
                    ldsm4(a[i], sA + off);
                }
#pragma unroll
                for (int p = 0; p < 2; ++p) {
                    const uint32_t off =
                        (uint32_t)((b_base_row + p * 16) * SKP + kc + b_col) * 2u;
                    uint32_t u[4];
                    ldsm4(u, sB + off);
                    b[2 * p][0] = u[0]; b[2 * p][1] = u[1];
                    b[2 * p + 1][0] = u[2]; b[2 * p + 1][1] = u[3];
                }
#pragma unroll
                for (int i = 0; i < 4; ++i)
#pragma unroll
                    for (int j = 0; j < 4; ++j)
                        hmma(acc[i][j], a[i], b[j]);
            }
            st ^= 1;
        }

        // ---- epilogue (overlaps next tile's stage-0 prefetch) ----
        {
            const int m0 = (tile >> 5) * BM;
            const int n0 = (tile & 31) * BN;
            const int g = lane >> 2, t = lane & 3;
#pragma unroll
            for (int i = 0; i < 4; ++i) {
#pragma unroll
                for (int j = 0; j < 4; ++j) {
                    const int row = m0 + wm * 64 + i * 16 + g;
                    const int col = n0 + wn * 32 + j * 8 + t * 2;
                    const float b0 = __ldg(&bias[col]);
                    const float b1 = __ldg(&bias[col + 1]);
                    float2 r0 = make_float2(acc[i][j][0] + b0, acc[i][j][1] + b1);
                    float2 r1 = make_float2(acc[i][j][2] + b0, acc[i][j][3] + b1);
                    *reinterpret_cast<float2*>(&Y[(size_t)row * N_DIM + col]) = r0;
                    *reinterpret_cast<float2*>(&Y[(size_t)(row + 8) * N_DIM + col]) = r1;
                    acc[i][j][0] = 0.f; acc[i][j][1] = 0.f;
                    acc[i][j][2] = 0.f; acc[i][j][3] = 0.f;
                }
            }
        }
    }
}

// ===========================================================================
extern "C" void kernel_launch(void* const* d_in, const int* in_sizes, int n_in,
                              void* d_out, int out_size) {
    const float* x = (const float*)d_in[0];
    const float* weight = (const float*)d_in[1];
    const float* bias = (const float*)d_in[2];
    const float* centroids = (const float*)d_in[3];
    float* Y = (float*)d_out;

    prologue<<<QBLK + CBLK, 256>>>(weight, centroids, x);

    cudaFuncSetAttribute(gemm_f16, cudaFuncAttributeMaxDynamicSharedMemorySize, SMEM_BYTES);
    gemm_f16<<<GRID, NTHR, SMEM_BYTES>>>(bias, Y);
}